// round 8
// baseline (speedup 1.0000x reference)
#include <cuda_runtime.h>
#include <cuda_bf16.h>
#include <cstdint>

#define B_SZ 16
#define LM   1024
#define LX   1024
#define D    768
#define NSPLIT 32

// ---------------- scratch (static; allocation-free) ----------------
__device__ unsigned short g_xTh[(size_t)B_SZ * D * LX];
__device__ unsigned short g_xTl[(size_t)B_SZ * D * LX];
__device__ unsigned short g_Gh [(size_t)B_SZ * D * D];
__device__ unsigned short g_Gl [(size_t)B_SZ * D * D];
__device__ unsigned short g_Ph [(size_t)B_SZ * D * D];
__device__ unsigned short g_Pl [(size_t)B_SZ * D * D];
__device__ unsigned short g_mh [(size_t)B_SZ * LM * D];
__device__ unsigned short g_ml [(size_t)B_SZ * LM * D];
__device__ unsigned short g_Wh [D * D];
__device__ unsigned short g_Wl [D * D];
__device__ float g_A   [(size_t)B_SZ * LM * D];
__device__ float g_part[(size_t)B_SZ * NSPLIT * 8 * 2 * D];

// triangular block enumeration for 6x6 upper (bx >= by)
__constant__ int c_trix[21] = {0,1,2,3,4,5, 1,2,3,4,5, 2,3,4,5, 3,4,5, 4,5, 5};
__constant__ int c_triy[21] = {0,0,0,0,0,0, 1,1,1,1,1, 2,2,2,2, 3,3,3, 4,4, 5};
// lower blocks to mirror-fill (RB > CB)
__constant__ int c_mrb[15] = {1,2,2,3,3,3,4,4,4,4,5,5,5,5,5};
__constant__ int c_mcb[15] = {0,0,1,0,1,2,0,1,2,3,0,1,2,3,4};

// ---------------- helpers ----------------
__device__ __forceinline__ uint32_t smem_u32(const void* p) {
    uint32_t a;
    asm("{ .reg .u64 t; cvta.to.shared.u64 t, %1; cvt.u32.u64 %0, t; }" : "=r"(a) : "l"(p));
    return a;
}
__device__ __forceinline__ void cpa16(uint32_t dst, const void* src) {
    asm volatile("cp.async.cg.shared.global [%0], [%1], 16;" :: "r"(dst), "l"(src));
}
#define CP_COMMIT() asm volatile("cp.async.commit_group;" ::: "memory")
#define CP_WAIT(n)  asm volatile("cp.async.wait_group %0;" :: "n"(n) : "memory")

__device__ __forceinline__ void ldm4(uint32_t* r, uint32_t addr) {
    asm volatile("ldmatrix.sync.aligned.m8n8.x4.shared.b16 {%0,%1,%2,%3}, [%4];"
                 : "=r"(r[0]), "=r"(r[1]), "=r"(r[2]), "=r"(r[3]) : "r"(addr));
}
__device__ __forceinline__ void mma16816(float* d, const uint32_t* a, uint32_t b0, uint32_t b1) {
    asm volatile("mma.sync.aligned.m16n8k16.row.col.f32.bf16.bf16.f32 "
                 "{%0,%1,%2,%3}, {%4,%5,%6,%7}, {%8,%9}, {%0,%1,%2,%3};"
                 : "+f"(d[0]), "+f"(d[1]), "+f"(d[2]), "+f"(d[3])
                 : "r"(a[0]), "r"(a[1]), "r"(a[2]), "r"(a[3]), "r"(b0), "r"(b1));
}
__device__ __forceinline__ void split1(float v, unsigned short& h, unsigned short& l) {
    __nv_bfloat16 hb = __float2bfloat16(v);
    __nv_bfloat16 lb = __float2bfloat16(v - __bfloat162float(hb));
    h = __bfloat16_as_ushort(hb);
    l = __bfloat16_as_ushort(lb);
}
__device__ __forceinline__ uint32_t packus(unsigned short a, unsigned short b) {
    return ((uint32_t)b << 16) | (uint32_t)a;
}

// ---------------------------------------------------------------------------
// bf16 split-GEMM: C[M,N] = A*B^T, A = Ah+Al, B = Bh+Bl (bf16 hi/lo),
// fp32 accumulate via mma.sync m16n8k16. CTA 128x128, K-chunk 64,
// 3-stage cp.async pipeline with one __syncthreads per chunk.
// ---------------------------------------------------------------------------
#define TILE_B 16384                 // 128 x 64 bf16
#define STAGE_B (4 * TILE_B)
#define GSMEM   (3 * STAGE_B)        // 192 KB

__global__ __launch_bounds__(256, 1) void gemm_bf16(
    const unsigned short* __restrict__ Ah, const unsigned short* __restrict__ Al,
    const unsigned short* __restrict__ Bh, const unsigned short* __restrict__ Bl,
    float* __restrict__ C, unsigned short* __restrict__ Ch, unsigned short* __restrict__ Cl,
    int N, int K, long sA, long sB, long sC, int split_out, int tri)
{
    extern __shared__ char smem[];
    const uint32_t sbt = smem_u32(smem);

    const int tid  = threadIdx.x;
    const int lane = tid & 31;
    const int wid  = tid >> 5;
    const int warp_m = wid & 1;
    const int warp_n = wid >> 1;
    int bx, by;
    if (tri) { bx = c_trix[blockIdx.x]; by = c_triy[blockIdx.x]; }
    else     { bx = blockIdx.x;         by = blockIdx.y; }
    const int brow = by * 128, bcol = bx * 128;
    const long bz = blockIdx.z;

    const int g  = tid >> 6;
    const int s  = tid & 63;
    const int rb = s >> 3;
    const int u  = s & 7;
    const unsigned short* src;
    {
        const unsigned short* s0 = Ah + bz * sA + (size_t)brow * K;
        const unsigned short* s1 = Al + bz * sA + (size_t)brow * K;
        const unsigned short* s2 = Bh + bz * sB + (size_t)bcol * K;
        const unsigned short* s3 = Bl + bz * sB + (size_t)bcol * K;
        src = (g == 0) ? s0 : (g == 1) ? s1 : (g == 2) ? s2 : s3;
    }

    const int NC = K >> 6;

    auto issue = [&](int c) {
        const uint32_t st = sbt + (uint32_t)(c % 3) * STAGE_B + g * TILE_B;
        const unsigned short* sp = src + c * 64 + u * 8;
#pragma unroll
        for (int i = 0; i < 16; i++) {
            int r = rb + 8 * i;
            cpa16(st + (uint32_t)((r * 8 + (u ^ (r & 7))) * 16), sp + (size_t)r * K);
        }
    };

    float acc[4][4][4];
#pragma unroll
    for (int a = 0; a < 4; a++)
#pragma unroll
        for (int b = 0; b < 4; b++)
#pragma unroll
            for (int q = 0; q < 4; q++) acc[a][b][q] = 0.f;

    const int a_r    = lane & 15;
    const int a_kbit = lane >> 4;
    const int b_r    = (lane & 7) + ((lane >> 4) << 3);
    const int b_kbit = (lane >> 3) & 1;

    issue(0); CP_COMMIT();
    issue(1); CP_COMMIT();

    for (int c = 0; c < NC; c++) {
        if (c < NC - 1) { CP_WAIT(1); } else { CP_WAIT(0); }
        __syncthreads();
        if (c + 2 < NC) { issue(c + 2); CP_COMMIT(); }

        const uint32_t stg = sbt + (uint32_t)(c % 3) * STAGE_B;
#pragma unroll
        for (int kk = 0; kk < 4; kk++) {
            uint32_t ah[4][4], al[4][4], bh[2][4], bl[2][4];
#pragma unroll
            for (int mt = 0; mt < 4; mt++) {
                int row = warp_m * 64 + mt * 16 + a_r;
                int ku  = kk * 2 + a_kbit;
                uint32_t off = (uint32_t)((row * 8 + (ku ^ (row & 7))) * 16);
                ldm4(ah[mt], stg + off);
                ldm4(al[mt], stg + TILE_B + off);
            }
#pragma unroll
            for (int p = 0; p < 2; p++) {
                int row = warp_n * 32 + p * 16 + b_r;
                int ku  = kk * 2 + b_kbit;
                uint32_t off = (uint32_t)((row * 8 + (ku ^ (row & 7))) * 16);
                ldm4(bh[p], stg + 2 * TILE_B + off);
                ldm4(bl[p], stg + 3 * TILE_B + off);
            }
#pragma unroll
            for (int mt = 0; mt < 4; mt++)
#pragma unroll
                for (int nt = 0; nt < 4; nt++) {
                    const int p = nt >> 1, q = (nt & 1) * 2;
                    mma16816(acc[mt][nt], ah[mt], bh[p][q], bh[p][q + 1]);
                    mma16816(acc[mt][nt], al[mt], bh[p][q], bh[p][q + 1]);
                    mma16816(acc[mt][nt], ah[mt], bl[p][q], bl[p][q + 1]);
                }
        }
    }

    // epilogue
    float*          Cb  = C  ? C  + bz * sC : nullptr;
    unsigned short* Chb = Ch + bz * sC;
    unsigned short* Clb = Cl + bz * sC;
#pragma unroll
    for (int mt = 0; mt < 4; mt++)
#pragma unroll
        for (int nt = 0; nt < 4; nt++) {
            const float* dd = acc[mt][nt];
            const int r   = brow + warp_m * 64 + mt * 16 + (lane >> 2);
            const int col = bcol + warp_n * 32 + nt * 8 + (lane & 3) * 2;
            if (!split_out) {
                *(float2*)&Cb[(size_t)r * N + col]       = make_float2(dd[0], dd[1]);
                *(float2*)&Cb[(size_t)(r + 8) * N + col] = make_float2(dd[2], dd[3]);
            } else {
                unsigned short h0, l0, h1, l1;
                split1(dd[0], h0, l0); split1(dd[1], h1, l1);
                *(uint32_t*)&Chb[(size_t)r * N + col] = packus(h0, h1);
                *(uint32_t*)&Clb[(size_t)r * N + col] = packus(l0, l1);
                split1(dd[2], h0, l0); split1(dd[3], h1, l1);
                *(uint32_t*)&Chb[(size_t)(r + 8) * N + col] = packus(h0, h1);
                *(uint32_t*)&Clb[(size_t)(r + 8) * N + col] = packus(l0, l1);
            }
        }
}

// ---------------------------------------------------------------------------
// Fill lower-triangle blocks of G (RB > CB) from upper: G[r][c] = G[c][r]
// ---------------------------------------------------------------------------
__global__ __launch_bounds__(256) void mirror_G()
{
    __shared__ unsigned short th[32][33], tl[32][33];
    const int b = blockIdx.z;
    const int p = blockIdx.y;
    const int t = blockIdx.x;                 // 0..15: 4x4 subtiles of 128x128
    const int r0 = c_mrb[p] * 128 + (t >> 2) * 32;
    const int c0 = c_mcb[p] * 128 + (t & 3) * 32;
    const int tx = threadIdx.x, ty = threadIdx.y;
    unsigned short* Gh = g_Gh + (size_t)b * D * D;
    unsigned short* Gl = g_Gl + (size_t)b * D * D;
#pragma unroll
    for (int i = 0; i < 32; i += 8) {
        th[ty + i][tx] = Gh[(size_t)(c0 + ty + i) * D + r0 + tx];
        tl[ty + i][tx] = Gl[(size_t)(c0 + ty + i) * D + r0 + tx];
    }
    __syncthreads();
#pragma unroll
    for (int i = 0; i < 32; i += 8) {
        Gh[(size_t)(r0 + ty + i) * D + c0 + tx] = th[tx][ty + i];
        Gl[(size_t)(r0 + ty + i) * D + c0 + tx] = tl[tx][ty + i];
    }
}

// ---------------------------------------------------------------------------
// x [B,LX,D] fp32 -> xTh/xTl [B,D,LX] bf16 hi/lo (fused transpose + split)
// ---------------------------------------------------------------------------
__global__ __launch_bounds__(256) void transpose_split_x(const float* __restrict__ x)
{
    __shared__ float t[32][33];
    const int b = blockIdx.z;
    const int l0 = blockIdx.x * 32, d0 = blockIdx.y * 32;
    const int tx = threadIdx.x, ty = threadIdx.y;
    const float* xp = x + (size_t)b * LX * D;
#pragma unroll
    for (int i = 0; i < 32; i += 8)
        t[ty + i][tx] = xp[(size_t)(l0 + ty + i) * D + d0 + tx];
    __syncthreads();
#pragma unroll
    for (int i = 0; i < 32; i += 8) {
        float v = t[tx][ty + i];
        unsigned short h, l; split1(v, h, l);
        size_t o = ((size_t)b * D + d0 + ty + i) * LX + l0 + tx;
        g_xTh[o] = h;
        g_xTl[o] = l;
    }
}

// fp32 -> bf16 hi/lo split (vectorized)
__global__ __launch_bounds__(256) void split_kernel(
    const float* __restrict__ src, unsigned short* __restrict__ h,
    unsigned short* __restrict__ l, int n4)
{
    int i = blockIdx.x * 256 + threadIdx.x;
    if (i >= n4) return;
    float4 v = ((const float4*)src)[i];
    unsigned short h0, l0, h1, l1, h2, l2, h3, l3;
    split1(v.x, h0, l0); split1(v.y, h1, l1);
    split1(v.z, h2, l2); split1(v.w, h3, l3);
    ((uint2*)h)[i] = make_uint2(packus(h0, h1), packus(h2, h3));
    ((uint2*)l)[i] = make_uint2(packus(l0, l1), packus(l2, l3));
}

// ---------------------------------------------------------------------------
// Fused beta + pooled partials. One warp per row, 8 warps/block,
// 4 rows per warp (LM/NSPLIT = 32 rows per block). Deterministic.
// beta = sum_d (mv-av)*w1 + mv*av*w2 ; partial[k] += beta * outputs[k]
// ---------------------------------------------------------------------------
#define DPW 24   // D / 32 elements per lane

__global__ __launch_bounds__(256) void beta_pooled(
    const float* __restrict__ mainp, const float* __restrict__ w)
{
    const int b  = blockIdx.y;
    const int sp = blockIdx.x;
    const int wid = threadIdx.x >> 5, lane = threadIdx.x & 31;
    const int m0 = sp * (LM / NSPLIT);

    float w1[DPW], w2[DPW], ss[DPW], sm[DPW];
#pragma unroll
    for (int j = 0; j < DPW; j++) {
        int d = lane + j * 32;
        w1[j] = w[d]; w2[j] = w[D + d];
        ss[j] = 0.f;  sm[j] = 0.f;
    }

#pragma unroll
    for (int rr = 0; rr < 4; rr++) {
        const int m = m0 + wid + rr * 8;
        const float* mp = mainp + ((size_t)b * LM + m) * D;
        const float* ap = g_A   + ((size_t)b * LM + m) * D;
        float mv[DPW], av[DPW], beta = 0.f;
#pragma unroll
        for (int j = 0; j < DPW; j++) {
            int d = lane + j * 32;
            mv[j] = mp[d]; av[j] = ap[d];
            beta += (mv[j] - av[j]) * w1[j] + (mv[j] * av[j]) * w2[j];
        }
#pragma unroll
        for (int o = 16; o; o >>= 1) beta += __shfl_xor_sync(0xffffffffu, beta, o);
#pragma unroll
        for (int j = 0; j < DPW; j++) {
            ss[j] += beta * (mv[j] - av[j]);
            sm[j] += beta * (mv[j] * av[j]);
        }
    }

    float* pp = g_part + ((size_t)((b * NSPLIT + sp) * 8 + wid)) * 2 * D;
#pragma unroll
    for (int j = 0; j < DPW; j++) {
        int d = lane + j * 32;
        pp[d]     = ss[j];
        pp[D + d] = sm[j];
    }
}

__global__ __launch_bounds__(256) void pooled_reduce(float* __restrict__ out)
{
    const int b = blockIdx.x;
    for (int k = threadIdx.x; k < 2 * D; k += 256) {
        float s = 0.f;
#pragma unroll 8
        for (int sp = 0; sp < NSPLIT * 8; sp++)
            s += g_part[((size_t)(b * NSPLIT * 8 + sp)) * 2 * D + k];
        out[(size_t)b * 2 * D + k] = s;
    }
}

// ---------------------------------------------------------------------------
extern "C" void kernel_launch(void* const* d_in, const int* in_sizes, int n_in,
                              void* d_out, int out_size)
{
    const float* mainp = (const float*)d_in[0];   // (B, LM, D)
    const float* xp    = (const float*)d_in[1];   // (B, LX, D)
    const float* Wp    = (const float*)d_in[2];   // (D, D)
    const float* wp    = (const float*)d_in[3];   // (2D, 1)
    float*       out   = (float*)d_out;           // (B, 2D)

    cudaFuncSetAttribute(gemm_bf16, cudaFuncAttributeMaxDynamicSharedMemorySize, GSMEM);

    unsigned short *xTh, *xTl, *Gh, *Gl, *Ph, *Pl, *mh, *ml, *Wh, *Wl;
    float *Aout;
    cudaGetSymbolAddress((void**)&xTh, g_xTh);
    cudaGetSymbolAddress((void**)&xTl, g_xTl);
    cudaGetSymbolAddress((void**)&Gh,  g_Gh);
    cudaGetSymbolAddress((void**)&Gl,  g_Gl);
    cudaGetSymbolAddress((void**)&Ph,  g_Ph);
    cudaGetSymbolAddress((void**)&Pl,  g_Pl);
    cudaGetSymbolAddress((void**)&mh,  g_mh);
    cudaGetSymbolAddress((void**)&ml,  g_ml);
    cudaGetSymbolAddress((void**)&Wh,  g_Wh);
    cudaGetSymbolAddress((void**)&Wl,  g_Wl);
    cudaGetSymbolAddress((void**)&Aout, g_A);

    // operand preparation (bf16 hi/lo)
    transpose_split_x<<<dim3(LX / 32, D / 32, B_SZ), dim3(32, 8)>>>(xp);
    split_kernel<<<(D * D / 4 + 255) / 256, 256>>>(Wp, Wh, Wl, D * D / 4);
    split_kernel<<<((int)((size_t)B_SZ * LM * D / 4) + 255) / 256, 256>>>(
        mainp, mh, ml, (int)((size_t)B_SZ * LM * D / 4));

    // 1) G_b = xT_b @ xT_b^T (symmetric: 21 upper blocks + mirror)
    gemm_bf16<<<dim3(21, 1, B_SZ), 256, GSMEM>>>(
        xTh, xTl, xTh, xTl, nullptr, Gh, Gl,
        D, LX, (long)D * LX, (long)D * LX, (long)D * D, 1, 1);
    mirror_G<<<dim3(16, 15, B_SZ), dim3(32, 8)>>>();

    // 2) P_b = G_b @ W^T     (D x D, K = D), W broadcast, split output
    gemm_bf16<<<dim3(D / 128, D / 128, B_SZ), 256, GSMEM>>>(
        Gh, Gl, Wh, Wl, nullptr, Ph, Pl,
        D, D, (long)D * D, 0L, (long)D * D, 1, 0);

    // 3) A_b = main_b @ P_b^T (LM x D, K = D), fp32 output
    gemm_bf16<<<dim3(D / 128, LM / 128, B_SZ), 256, GSMEM>>>(
        mh, ml, Ph, Pl, Aout, Ph, Pl,
        D, D, (long)LM * D, (long)D * D, (long)LM * D, 0, 0);

    // 4) fused beta + pooled partials, then deterministic reduce
    beta_pooled<<<dim3(NSPLIT, B_SZ), 256>>>(mainp, wp);
    pooled_reduce<<<B_SZ, 256>>>(out);
}

// round 12
// speedup vs baseline: 1.1838x; 1.1838x over previous
#include <cuda_runtime.h>
#include <cuda_bf16.h>
#include <cstdint>

#define B_SZ 16
#define LM   1024
#define LX   1024
#define D    768
#define NSPLIT 32

// ---------------- scratch (static; allocation-free) ----------------
__device__ unsigned short g_xTh[(size_t)B_SZ * D * LX];
__device__ unsigned short g_xTl[(size_t)B_SZ * D * LX];
__device__ unsigned short g_Gh [(size_t)B_SZ * D * D];
__device__ unsigned short g_Gl [(size_t)B_SZ * D * D];
__device__ unsigned short g_Ph [(size_t)B_SZ * D * D];
__device__ unsigned short g_Pl [(size_t)B_SZ * D * D];
__device__ unsigned short g_mh [(size_t)B_SZ * LM * D];
__device__ unsigned short g_ml [(size_t)B_SZ * LM * D];
__device__ unsigned short g_Wh [D * D];
__device__ unsigned short g_Wl [D * D];
__device__ float g_A   [(size_t)B_SZ * LM * D];
__device__ float g_beta[B_SZ * LM];
__device__ float g_part[B_SZ * NSPLIT * 2 * D];

// triangular block enumeration for 6x6 upper (bx >= by)
__constant__ int c_trix[21] = {0,1,2,3,4,5, 1,2,3,4,5, 2,3,4,5, 3,4,5, 4,5, 5};
__constant__ int c_triy[21] = {0,0,0,0,0,0, 1,1,1,1,1, 2,2,2,2, 3,3,3, 4,4, 5};
// lower blocks to mirror-fill (RB > CB)
__constant__ int c_mrb[15] = {1,2,2,3,3,3,4,4,4,4,5,5,5,5,5};
__constant__ int c_mcb[15] = {0,0,1,0,1,2,0,1,2,3,0,1,2,3,4};

// ---------------- helpers ----------------
__device__ __forceinline__ uint32_t smem_u32(const void* p) {
    uint32_t a;
    asm("{ .reg .u64 t; cvta.to.shared.u64 t, %1; cvt.u32.u64 %0, t; }" : "=r"(a) : "l"(p));
    return a;
}
__device__ __forceinline__ void cpa16(uint32_t dst, const void* src) {
    asm volatile("cp.async.cg.shared.global [%0], [%1], 16;" :: "r"(dst), "l"(src));
}
#define CP_COMMIT() asm volatile("cp.async.commit_group;" ::: "memory")
#define CP_WAIT(n)  asm volatile("cp.async.wait_group %0;" :: "n"(n) : "memory")

__device__ __forceinline__ void ldm4(uint32_t* r, uint32_t addr) {
    asm volatile("ldmatrix.sync.aligned.m8n8.x4.shared.b16 {%0,%1,%2,%3}, [%4];"
                 : "=r"(r[0]), "=r"(r[1]), "=r"(r[2]), "=r"(r[3]) : "r"(addr));
}
__device__ __forceinline__ void mma16816(float* d, const uint32_t* a, uint32_t b0, uint32_t b1) {
    asm volatile("mma.sync.aligned.m16n8k16.row.col.f32.bf16.bf16.f32 "
                 "{%0,%1,%2,%3}, {%4,%5,%6,%7}, {%8,%9}, {%0,%1,%2,%3};"
                 : "+f"(d[0]), "+f"(d[1]), "+f"(d[2]), "+f"(d[3])
                 : "r"(a[0]), "r"(a[1]), "r"(a[2]), "r"(a[3]), "r"(b0), "r"(b1));
}
__device__ __forceinline__ void split1(float v, unsigned short& h, unsigned short& l) {
    __nv_bfloat16 hb = __float2bfloat16(v);
    __nv_bfloat16 lb = __float2bfloat16(v - __bfloat162float(hb));
    h = __bfloat16_as_ushort(hb);
    l = __bfloat16_as_ushort(lb);
}
__device__ __forceinline__ uint32_t packus(unsigned short a, unsigned short b) {
    return ((uint32_t)b << 16) | (uint32_t)a;
}

// ---------------------------------------------------------------------------
// bf16 split-GEMM: C[M,N] = A*B^T, A = Ah+Al, B = Bh+Bl (bf16 hi/lo),
// fp32 accumulate via mma.sync m16n8k16. CTA 128x128, K-chunk 64,
// 2-stage cp.async pipeline (proven 65.5% tensor busy).
// ---------------------------------------------------------------------------
#define TILE_B 16384                 // 128 x 64 bf16
#define STAGE_B (4 * TILE_B)
#define GSMEM   (2 * STAGE_B)        // 128 KB

__global__ __launch_bounds__(256, 1) void gemm_bf16(
    const unsigned short* __restrict__ Ah, const unsigned short* __restrict__ Al,
    const unsigned short* __restrict__ Bh, const unsigned short* __restrict__ Bl,
    float* __restrict__ C, unsigned short* __restrict__ Ch, unsigned short* __restrict__ Cl,
    int N, int K, long sA, long sB, long sC, int split_out, int tri)
{
    extern __shared__ char smem[];
    const uint32_t sbt = smem_u32(smem);

    const int tid  = threadIdx.x;
    const int lane = tid & 31;
    const int wid  = tid >> 5;
    const int warp_m = wid & 1;        // 2 warps along M (64 rows each)
    const int warp_n = wid >> 1;       // 4 warps along N (32 cols each)
    int bx, by;
    if (tri) { bx = c_trix[blockIdx.x]; by = c_triy[blockIdx.x]; }
    else     { bx = blockIdx.x;         by = blockIdx.y; }
    const int brow = by * 128, bcol = bx * 128;
    const long bz = blockIdx.z;

    const int g  = tid >> 6;
    const int s  = tid & 63;
    const int rb = s >> 3;
    const int u  = s & 7;
    const unsigned short* src;
    {
        const unsigned short* s0 = Ah + bz * sA + (size_t)brow * K;
        const unsigned short* s1 = Al + bz * sA + (size_t)brow * K;
        const unsigned short* s2 = Bh + bz * sB + (size_t)bcol * K;
        const unsigned short* s3 = Bl + bz * sB + (size_t)bcol * K;
        src = (g == 0) ? s0 : (g == 1) ? s1 : (g == 2) ? s2 : s3;
    }

    const int NC = K >> 6;

    auto issue = [&](int c) {
        const uint32_t st = sbt + (c & 1) * STAGE_B + g * TILE_B;
        const unsigned short* sp = src + c * 64 + u * 8;
#pragma unroll
        for (int i = 0; i < 16; i++) {
            int r = rb + 8 * i;
            cpa16(st + (uint32_t)((r * 8 + (u ^ (r & 7))) * 16), sp + (size_t)r * K);
        }
    };

    float acc[4][4][4];
#pragma unroll
    for (int a = 0; a < 4; a++)
#pragma unroll
        for (int b = 0; b < 4; b++)
#pragma unroll
            for (int q = 0; q < 4; q++) acc[a][b][q] = 0.f;

    const int a_r    = lane & 15;
    const int a_kbit = lane >> 4;
    const int b_r    = (lane & 7) + ((lane >> 4) << 3);
    const int b_kbit = (lane >> 3) & 1;

    issue(0); CP_COMMIT();

    for (int c = 0; c < NC; c++) {
        if (c + 1 < NC) { issue(c + 1); CP_COMMIT(); CP_WAIT(1); }
        else            { CP_WAIT(0); }
        __syncthreads();

        const uint32_t stg = sbt + (c & 1) * STAGE_B;
#pragma unroll
        for (int kk = 0; kk < 4; kk++) {
            uint32_t ah[4][4], al[4][4], bh[2][4], bl[2][4];
#pragma unroll
            for (int mt = 0; mt < 4; mt++) {
                int row = warp_m * 64 + mt * 16 + a_r;
                int ku  = kk * 2 + a_kbit;
                uint32_t off = (uint32_t)((row * 8 + (ku ^ (row & 7))) * 16);
                ldm4(ah[mt], stg + off);
                ldm4(al[mt], stg + TILE_B + off);
            }
#pragma unroll
            for (int p = 0; p < 2; p++) {
                int row = warp_n * 32 + p * 16 + b_r;
                int ku  = kk * 2 + b_kbit;
                uint32_t off = (uint32_t)((row * 8 + (ku ^ (row & 7))) * 16);
                ldm4(bh[p], stg + 2 * TILE_B + off);
                ldm4(bl[p], stg + 3 * TILE_B + off);
            }
#pragma unroll
            for (int mt = 0; mt < 4; mt++)
#pragma unroll
                for (int nt = 0; nt < 4; nt++) {
                    const int p = nt >> 1, q = (nt & 1) * 2;
                    mma16816(acc[mt][nt], ah[mt], bh[p][q], bh[p][q + 1]);
                    mma16816(acc[mt][nt], al[mt], bh[p][q], bh[p][q + 1]);
                    mma16816(acc[mt][nt], ah[mt], bl[p][q], bl[p][q + 1]);
                }
        }
        __syncthreads();
    }

    // epilogue
    float*          Cb  = C  ? C  + bz * sC : nullptr;
    unsigned short* Chb = Ch + bz * sC;
    unsigned short* Clb = Cl + bz * sC;
#pragma unroll
    for (int mt = 0; mt < 4; mt++)
#pragma unroll
        for (int nt = 0; nt < 4; nt++) {
            const float* dd = acc[mt][nt];
            const int r   = brow + warp_m * 64 + mt * 16 + (lane >> 2);
            const int col = bcol + warp_n * 32 + nt * 8 + (lane & 3) * 2;
            if (!split_out) {
                *(float2*)&Cb[(size_t)r * N + col]       = make_float2(dd[0], dd[1]);
                *(float2*)&Cb[(size_t)(r + 8) * N + col] = make_float2(dd[2], dd[3]);
            } else {
                unsigned short h0, l0, h1, l1;
                split1(dd[0], h0, l0); split1(dd[1], h1, l1);
                *(uint32_t*)&Chb[(size_t)r * N + col] = packus(h0, h1);
                *(uint32_t*)&Clb[(size_t)r * N + col] = packus(l0, l1);
                split1(dd[2], h0, l0); split1(dd[3], h1, l1);
                *(uint32_t*)&Chb[(size_t)(r + 8) * N + col] = packus(h0, h1);
                *(uint32_t*)&Clb[(size_t)(r + 8) * N + col] = packus(l0, l1);
            }
        }
}

// ---------------------------------------------------------------------------
// Fill lower-triangle blocks of G (RB > CB) from upper: G[r][c] = G[c][r]
// ---------------------------------------------------------------------------
__global__ __launch_bounds__(256) void mirror_G()
{
    __shared__ unsigned short th[32][33], tl[32][33];
    const int b = blockIdx.z;
    const int p = blockIdx.y;
    const int t = blockIdx.x;                 // 0..15: 4x4 subtiles of 128x128
    const int r0 = c_mrb[p] * 128 + (t >> 2) * 32;
    const int c0 = c_mcb[p] * 128 + (t & 3) * 32;
    const int tx = threadIdx.x, ty = threadIdx.y;
    unsigned short* Gh = g_Gh + (size_t)b * D * D;
    unsigned short* Gl = g_Gl + (size_t)b * D * D;
#pragma unroll
    for (int i = 0; i < 32; i += 8) {
        th[ty + i][tx] = Gh[(size_t)(c0 + ty + i) * D + r0 + tx];
        tl[ty + i][tx] = Gl[(size_t)(c0 + ty + i) * D + r0 + tx];
    }
    __syncthreads();
#pragma unroll
    for (int i = 0; i < 32; i += 8) {
        Gh[(size_t)(r0 + ty + i) * D + c0 + tx] = th[tx][ty + i];
        Gl[(size_t)(r0 + ty + i) * D + c0 + tx] = tl[tx][ty + i];
    }
}

// ---------------------------------------------------------------------------
// x [B,LX,D] fp32 -> xTh/xTl [B,D,LX] bf16 hi/lo (fused transpose + split)
// ---------------------------------------------------------------------------
__global__ __launch_bounds__(256) void transpose_split_x(const float* __restrict__ x)
{
    __shared__ float t[32][33];
    const int b = blockIdx.z;
    const int l0 = blockIdx.x * 32, d0 = blockIdx.y * 32;
    const int tx = threadIdx.x, ty = threadIdx.y;
    const float* xp = x + (size_t)b * LX * D;
#pragma unroll
    for (int i = 0; i < 32; i += 8)
        t[ty + i][tx] = xp[(size_t)(l0 + ty + i) * D + d0 + tx];
    __syncthreads();
#pragma unroll
    for (int i = 0; i < 32; i += 8) {
        float v = t[tx][ty + i];
        unsigned short h, l; split1(v, h, l);
        size_t o = ((size_t)b * D + d0 + ty + i) * LX + l0 + tx;
        g_xTh[o] = h;
        g_xTl[o] = l;
    }
}

// fp32 -> bf16 hi/lo split (vectorized)
__global__ __launch_bounds__(256) void split_kernel(
    const float* __restrict__ src, unsigned short* __restrict__ h,
    unsigned short* __restrict__ l, int n4)
{
    int i = blockIdx.x * 256 + threadIdx.x;
    if (i >= n4) return;
    float4 v = ((const float4*)src)[i];
    unsigned short h0, l0, h1, l1, h2, l2, h3, l3;
    split1(v.x, h0, l0); split1(v.y, h1, l1);
    split1(v.z, h2, l2); split1(v.w, h3, l3);
    ((uint2*)h)[i] = make_uint2(packus(h0, h1), packus(h2, h3));
    ((uint2*)l)[i] = make_uint2(packus(l0, l1), packus(l2, l3));
}

// ---------------------------------------------------------------------------
// beta[b,m] = sum_d (main-A)*w1 + (main*A)*w2
// ---------------------------------------------------------------------------
__global__ __launch_bounds__(256) void beta_kernel(
    const float* __restrict__ mainp, const float* __restrict__ w)
{
    const int bm = blockIdx.x;
    const float* mp = mainp + (size_t)bm * D;
    const float* ap = g_A   + (size_t)bm * D;

    float sum = 0.f;
    for (int d = threadIdx.x; d < D; d += 256) {
        float mv = mp[d], av = ap[d];
        sum += (mv - av) * w[d] + (mv * av) * w[D + d];
    }
#pragma unroll
    for (int o = 16; o; o >>= 1) sum += __shfl_xor_sync(0xffffffffu, sum, o);

    __shared__ float red[8];
    if ((threadIdx.x & 31) == 0) red[threadIdx.x >> 5] = sum;
    __syncthreads();
    if (threadIdx.x < 8) {
        float v = red[threadIdx.x];
#pragma unroll
        for (int o = 4; o; o >>= 1) v += __shfl_xor_sync(0xffu, v, o);
        if (threadIdx.x == 0) g_beta[bm] = v;
    }
}

__global__ __launch_bounds__(768) void pooled_partial(const float* __restrict__ mainp)
{
    const int b  = blockIdx.y;
    const int sp = blockIdx.x;
    const int d  = threadIdx.x;
    const int m0 = sp * (LM / NSPLIT);

    const float* mp = mainp  + ((size_t)b * LM + m0) * D + d;
    const float* ap = g_A    + ((size_t)b * LM + m0) * D + d;
    const float* bp = g_beta + (size_t)b * LM + m0;

    float ss = 0.f, sm = 0.f;
#pragma unroll 4
    for (int i = 0; i < LM / NSPLIT; i++) {
        float bt = bp[i];
        float mv = mp[(size_t)i * D];
        float av = ap[(size_t)i * D];
        ss += bt * (mv - av);
        sm += bt * (mv * av);
    }
    float* pp = g_part + (size_t)(b * NSPLIT + sp) * 2 * D;
    pp[d]     = ss;
    pp[D + d] = sm;
}

__global__ __launch_bounds__(256) void pooled_reduce(float* __restrict__ out)
{
    const int b = blockIdx.x;
    for (int k = threadIdx.x; k < 2 * D; k += 256) {
        float s = 0.f;
#pragma unroll
        for (int sp = 0; sp < NSPLIT; sp++)
            s += g_part[(size_t)(b * NSPLIT + sp) * 2 * D + k];
        out[(size_t)b * 2 * D + k] = s;
    }
}

// ---------------------------------------------------------------------------
extern "C" void kernel_launch(void* const* d_in, const int* in_sizes, int n_in,
                              void* d_out, int out_size)
{
    const float* mainp = (const float*)d_in[0];   // (B, LM, D)
    const float* xp    = (const float*)d_in[1];   // (B, LX, D)
    const float* Wp    = (const float*)d_in[2];   // (D, D)
    const float* wp    = (const float*)d_in[3];   // (2D, 1)
    float*       out   = (float*)d_out;           // (B, 2D)

    cudaFuncSetAttribute(gemm_bf16, cudaFuncAttributeMaxDynamicSharedMemorySize, GSMEM);

    unsigned short *xTh, *xTl, *Gh, *Gl, *Ph, *Pl, *mh, *ml, *Wh, *Wl;
    float *Aout;
    cudaGetSymbolAddress((void**)&xTh, g_xTh);
    cudaGetSymbolAddress((void**)&xTl, g_xTl);
    cudaGetSymbolAddress((void**)&Gh,  g_Gh);
    cudaGetSymbolAddress((void**)&Gl,  g_Gl);
    cudaGetSymbolAddress((void**)&Ph,  g_Ph);
    cudaGetSymbolAddress((void**)&Pl,  g_Pl);
    cudaGetSymbolAddress((void**)&mh,  g_mh);
    cudaGetSymbolAddress((void**)&ml,  g_ml);
    cudaGetSymbolAddress((void**)&Wh,  g_Wh);
    cudaGetSymbolAddress((void**)&Wl,  g_Wl);
    cudaGetSymbolAddress((void**)&Aout, g_A);

    // operand preparation (bf16 hi/lo)
    transpose_split_x<<<dim3(LX / 32, D / 32, B_SZ), dim3(32, 8)>>>(xp);
    split_kernel<<<(D * D / 4 + 255) / 256, 256>>>(Wp, Wh, Wl, D * D / 4);
    split_kernel<<<((int)((size_t)B_SZ * LM * D / 4) + 255) / 256, 256>>>(
        mainp, mh, ml, (int)((size_t)B_SZ * LM * D / 4));

    // 1) G_b = xT_b @ xT_b^T (symmetric: 21 upper blocks + mirror)
    gemm_bf16<<<dim3(21, 1, B_SZ), 256, GSMEM>>>(
        xTh, xTl, xTh, xTl, nullptr, Gh, Gl,
        D, LX, (long)D * LX, (long)D * LX, (long)D * D, 1, 1);
    mirror_G<<<dim3(16, 15, B_SZ), dim3(32, 8)>>>();

    // 2) P_b = G_b @ W^T     (D x D, K = D), W broadcast, split output
    gemm_bf16<<<dim3(D / 128, D / 128, B_SZ), 256, GSMEM>>>(
        Gh, Gl, Wh, Wl, nullptr, Ph, Pl,
        D, D, (long)D * D, 0L, (long)D * D, 1, 0);

    // 3) A_b = main_b @ P_b^T (LM x D, K = D), fp32 output
    gemm_bf16<<<dim3(D / 128, LM / 128, B_SZ), 256, GSMEM>>>(
        mh, ml, Ph, Pl, Aout, Ph, Pl,
        D, D, (long)LM * D, (long)D * D, (long)LM * D, 0, 0);

    // 4) beta, then pooled partials + deterministic reduce
    beta_kernel<<<B_SZ * LM, 256>>>(mainp, wp);
    pooled_partial<<<dim3(NSPLIT, B_SZ), 768>>>(mainp);
    pooled_reduce<<<B_SZ, 256>>>(out);
}

// round 13
// speedup vs baseline: 1.2301x; 1.0392x over previous
#include <cuda_runtime.h>
#include <cuda_bf16.h>
#include <cstdint>

#define B_SZ 16
#define LM   1024
#define LX   1024
#define D    768
#define NSPLIT 32

// ---------------- scratch (static; allocation-free) ----------------
__device__ unsigned short g_xTh[(size_t)B_SZ * D * LX];
__device__ unsigned short g_xTl[(size_t)B_SZ * D * LX];
__device__ unsigned short g_Gh [(size_t)B_SZ * D * D];
__device__ unsigned short g_Gl [(size_t)B_SZ * D * D];
__device__ unsigned short g_Ph [(size_t)B_SZ * D * D];
__device__ unsigned short g_Pl [(size_t)B_SZ * D * D];
__device__ unsigned short g_mh [(size_t)B_SZ * LM * D];
__device__ unsigned short g_ml [(size_t)B_SZ * LM * D];
__device__ unsigned short g_Wh [D * D];
__device__ unsigned short g_Wl [D * D];
__device__ float g_A   [(size_t)B_SZ * LM * D];
__device__ float g_part[B_SZ * NSPLIT * 2 * D];

// triangular block enumeration for 6x6 upper (bx >= by)
__constant__ int c_trix[21] = {0,1,2,3,4,5, 1,2,3,4,5, 2,3,4,5, 3,4,5, 4,5, 5};
__constant__ int c_triy[21] = {0,0,0,0,0,0, 1,1,1,1,1, 2,2,2,2, 3,3,3, 4,4, 5};
// lower blocks to mirror-fill (RB > CB)
__constant__ int c_mrb[15] = {1,2,2,3,3,3,4,4,4,4,5,5,5,5,5};
__constant__ int c_mcb[15] = {0,0,1,0,1,2,0,1,2,3,0,1,2,3,4};

// ---------------- helpers ----------------
__device__ __forceinline__ uint32_t smem_u32(const void* p) {
    uint32_t a;
    asm("{ .reg .u64 t; cvta.to.shared.u64 t, %1; cvt.u32.u64 %0, t; }" : "=r"(a) : "l"(p));
    return a;
}
__device__ __forceinline__ void cpa16(uint32_t dst, const void* src) {
    asm volatile("cp.async.cg.shared.global [%0], [%1], 16;" :: "r"(dst), "l"(src));
}
#define CP_COMMIT() asm volatile("cp.async.commit_group;" ::: "memory")
#define CP_WAIT(n)  asm volatile("cp.async.wait_group %0;" :: "n"(n) : "memory")

__device__ __forceinline__ void ldm4(uint32_t* r, uint32_t addr) {
    asm volatile("ldmatrix.sync.aligned.m8n8.x4.shared.b16 {%0,%1,%2,%3}, [%4];"
                 : "=r"(r[0]), "=r"(r[1]), "=r"(r[2]), "=r"(r[3]) : "r"(addr));
}
__device__ __forceinline__ void mma16816(float* d, const uint32_t* a, uint32_t b0, uint32_t b1) {
    asm volatile("mma.sync.aligned.m16n8k16.row.col.f32.bf16.bf16.f32 "
                 "{%0,%1,%2,%3}, {%4,%5,%6,%7}, {%8,%9}, {%0,%1,%2,%3};"
                 : "+f"(d[0]), "+f"(d[1]), "+f"(d[2]), "+f"(d[3])
                 : "r"(a[0]), "r"(a[1]), "r"(a[2]), "r"(a[3]), "r"(b0), "r"(b1));
}
__device__ __forceinline__ void split1(float v, unsigned short& h, unsigned short& l) {
    __nv_bfloat16 hb = __float2bfloat16(v);
    __nv_bfloat16 lb = __float2bfloat16(v - __bfloat162float(hb));
    h = __bfloat16_as_ushort(hb);
    l = __bfloat16_as_ushort(lb);
}
__device__ __forceinline__ uint32_t packus(unsigned short a, unsigned short b) {
    return ((uint32_t)b << 16) | (uint32_t)a;
}

// ---------------------------------------------------------------------------
// bf16 split-GEMM: C[M,N] = A*B^T, A = Ah+Al, B = Bh+Bl (bf16 hi/lo),
// fp32 accumulate via mma.sync m16n8k16. CTA 128x128, K-chunk 64,
// 2-stage cp.async pipeline; loads for chunk c+1 spread across the kk loop.
// ---------------------------------------------------------------------------
#define TILE_B 16384                 // 128 x 64 bf16
#define STAGE_B (4 * TILE_B)
#define GSMEM   (2 * STAGE_B)        // 128 KB

__global__ __launch_bounds__(256, 1) void gemm_bf16(
    const unsigned short* __restrict__ Ah, const unsigned short* __restrict__ Al,
    const unsigned short* __restrict__ Bh, const unsigned short* __restrict__ Bl,
    float* __restrict__ C, unsigned short* __restrict__ Ch, unsigned short* __restrict__ Cl,
    int N, int K, long sA, long sB, long sC, int split_out, int tri)
{
    extern __shared__ char smem[];
    const uint32_t sbt = smem_u32(smem);

    const int tid  = threadIdx.x;
    const int lane = tid & 31;
    const int wid  = tid >> 5;
    const int warp_m = wid & 1;        // 2 warps along M (64 rows each)
    const int warp_n = wid >> 1;       // 4 warps along N (32 cols each)
    int bx, by;
    if (tri) { bx = c_trix[blockIdx.x]; by = c_triy[blockIdx.x]; }
    else     { bx = blockIdx.x;         by = blockIdx.y; }
    const int brow = by * 128, bcol = bx * 128;
    const long bz = blockIdx.z;

    const int g  = tid >> 6;
    const int s  = tid & 63;
    const int rb = s >> 3;
    const int u  = s & 7;
    const unsigned short* src;
    {
        const unsigned short* s0 = Ah + bz * sA + (size_t)brow * K;
        const unsigned short* s1 = Al + bz * sA + (size_t)brow * K;
        const unsigned short* s2 = Bh + bz * sB + (size_t)bcol * K;
        const unsigned short* s3 = Bl + bz * sB + (size_t)bcol * K;
        src = (g == 0) ? s0 : (g == 1) ? s1 : (g == 2) ? s2 : s3;
    }

    const int NC = K >> 6;

    // issue quarter q (4 of 16 LDGSTS) of chunk c's tile
    auto issueq = [&](int c, int q) {
        const uint32_t st = sbt + (c & 1) * STAGE_B + g * TILE_B;
        const unsigned short* sp = src + c * 64 + u * 8;
#pragma unroll
        for (int i = q * 4; i < q * 4 + 4; i++) {
            int r = rb + 8 * i;
            cpa16(st + (uint32_t)((r * 8 + (u ^ (r & 7))) * 16), sp + (size_t)r * K);
        }
    };

    float acc[4][4][4];
#pragma unroll
    for (int a = 0; a < 4; a++)
#pragma unroll
        for (int b = 0; b < 4; b++)
#pragma unroll
            for (int q = 0; q < 4; q++) acc[a][b][q] = 0.f;

    const int a_r    = lane & 15;
    const int a_kbit = lane >> 4;
    const int b_r    = (lane & 7) + ((lane >> 4) << 3);
    const int b_kbit = (lane >> 3) & 1;

#pragma unroll
    for (int q = 0; q < 4; q++) issueq(0, q);
    CP_COMMIT();

    for (int c = 0; c < NC; c++) {
        CP_WAIT(0);
        __syncthreads();     // all threads' chunk-c data resident; all chunk c-1 reads done

        const uint32_t stg = sbt + (c & 1) * STAGE_B;
#pragma unroll
        for (int kk = 0; kk < 4; kk++) {
            if (c + 1 < NC) issueq(c + 1, kk);
            uint32_t ah[4][4], al[4][4], bh[2][4], bl[2][4];
#pragma unroll
            for (int mt = 0; mt < 4; mt++) {
                int row = warp_m * 64 + mt * 16 + a_r;
                int ku  = kk * 2 + a_kbit;
                uint32_t off = (uint32_t)((row * 8 + (ku ^ (row & 7))) * 16);
                ldm4(ah[mt], stg + off);
                ldm4(al[mt], stg + TILE_B + off);
            }
#pragma unroll
            for (int p = 0; p < 2; p++) {
                int row = warp_n * 32 + p * 16 + b_r;
                int ku  = kk * 2 + b_kbit;
                uint32_t off = (uint32_t)((row * 8 + (ku ^ (row & 7))) * 16);
                ldm4(bh[p], stg + 2 * TILE_B + off);
                ldm4(bl[p], stg + 3 * TILE_B + off);
            }
#pragma unroll
            for (int mt = 0; mt < 4; mt++)
#pragma unroll
                for (int nt = 0; nt < 4; nt++) {
                    const int p = nt >> 1, q = (nt & 1) * 2;
                    mma16816(acc[mt][nt], ah[mt], bh[p][q], bh[p][q + 1]);
                    mma16816(acc[mt][nt], al[mt], bh[p][q], bh[p][q + 1]);
                    mma16816(acc[mt][nt], ah[mt], bl[p][q], bl[p][q + 1]);
                }
        }
        if (c + 1 < NC) CP_COMMIT();
    }

    // epilogue
    float*          Cb  = C  ? C  + bz * sC : nullptr;
    unsigned short* Chb = Ch + bz * sC;
    unsigned short* Clb = Cl + bz * sC;
#pragma unroll
    for (int mt = 0; mt < 4; mt++)
#pragma unroll
        for (int nt = 0; nt < 4; nt++) {
            const float* dd = acc[mt][nt];
            const int r   = brow + warp_m * 64 + mt * 16 + (lane >> 2);
            const int col = bcol + warp_n * 32 + nt * 8 + (lane & 3) * 2;
            if (!split_out) {
                *(float2*)&Cb[(size_t)r * N + col]       = make_float2(dd[0], dd[1]);
                *(float2*)&Cb[(size_t)(r + 8) * N + col] = make_float2(dd[2], dd[3]);
            } else {
                unsigned short h0, l0, h1, l1;
                split1(dd[0], h0, l0); split1(dd[1], h1, l1);
                *(uint32_t*)&Chb[(size_t)r * N + col] = packus(h0, h1);
                *(uint32_t*)&Clb[(size_t)r * N + col] = packus(l0, l1);
                split1(dd[2], h0, l0); split1(dd[3], h1, l1);
                *(uint32_t*)&Chb[(size_t)(r + 8) * N + col] = packus(h0, h1);
                *(uint32_t*)&Clb[(size_t)(r + 8) * N + col] = packus(l0, l1);
            }
        }
}

// ---------------------------------------------------------------------------
// Fill lower-triangle blocks of G (RB > CB) from upper: G[r][c] = G[c][r]
// ---------------------------------------------------------------------------
__global__ __launch_bounds__(256) void mirror_G()
{
    __shared__ unsigned short th[32][33], tl[32][33];
    const int b = blockIdx.z;
    const int p = blockIdx.y;
    const int t = blockIdx.x;                 // 0..15: 4x4 subtiles of 128x128
    const int r0 = c_mrb[p] * 128 + (t >> 2) * 32;
    const int c0 = c_mcb[p] * 128 + (t & 3) * 32;
    const int tx = threadIdx.x, ty = threadIdx.y;
    unsigned short* Gh = g_Gh + (size_t)b * D * D;
    unsigned short* Gl = g_Gl + (size_t)b * D * D;
#pragma unroll
    for (int i = 0; i < 32; i += 8) {
        th[ty + i][tx] = Gh[(size_t)(c0 + ty + i) * D + r0 + tx];
        tl[ty + i][tx] = Gl[(size_t)(c0 + ty + i) * D + r0 + tx];
    }
    __syncthreads();
#pragma unroll
    for (int i = 0; i < 32; i += 8) {
        Gh[(size_t)(r0 + ty + i) * D + c0 + tx] = th[tx][ty + i];
        Gl[(size_t)(r0 + ty + i) * D + c0 + tx] = tl[tx][ty + i];
    }
}

// ---------------------------------------------------------------------------
// x [B,LX,D] fp32 -> xTh/xTl [B,D,LX] bf16 hi/lo (fused transpose + split)
// ---------------------------------------------------------------------------
__global__ __launch_bounds__(256) void transpose_split_x(const float* __restrict__ x)
{
    __shared__ float t[32][33];
    const int b = blockIdx.z;
    const int l0 = blockIdx.x * 32, d0 = blockIdx.y * 32;
    const int tx = threadIdx.x, ty = threadIdx.y;
    const float* xp = x + (size_t)b * LX * D;
#pragma unroll
    for (int i = 0; i < 32; i += 8)
        t[ty + i][tx] = xp[(size_t)(l0 + ty + i) * D + d0 + tx];
    __syncthreads();
#pragma unroll
    for (int i = 0; i < 32; i += 8) {
        float v = t[tx][ty + i];
        unsigned short h, l; split1(v, h, l);
        size_t o = ((size_t)b * D + d0 + ty + i) * LX + l0 + tx;
        g_xTh[o] = h;
        g_xTl[o] = l;
    }
}

// fp32 -> bf16 hi/lo split (vectorized)
__global__ __launch_bounds__(256) void split_kernel(
    const float* __restrict__ src, unsigned short* __restrict__ h,
    unsigned short* __restrict__ l, int n4)
{
    int i = blockIdx.x * 256 + threadIdx.x;
    if (i >= n4) return;
    float4 v = ((const float4*)src)[i];
    unsigned short h0, l0, h1, l1, h2, l2, h3, l3;
    split1(v.x, h0, l0); split1(v.y, h1, l1);
    split1(v.z, h2, l2); split1(v.w, h3, l3);
    ((uint2*)h)[i] = make_uint2(packus(h0, h1), packus(h2, h3));
    ((uint2*)l)[i] = make_uint2(packus(l0, l1), packus(l2, l3));
}

// ---------------------------------------------------------------------------
// Fused beta + pooled partials. Block = 256 threads handles 32 rows.
// Phase 1: 8 warps x 4 rows — beta per row (values not retained), to smem.
// Phase 2: pooled_partial column layout (3 d-cols/thread), rows re-read
// from L2 (just touched in phase 1). Deterministic, no atomics.
// ---------------------------------------------------------------------------
__global__ __launch_bounds__(256) void beta_pooled_fused(
    const float* __restrict__ mainp, const float* __restrict__ w)
{
    __shared__ float sbeta[32];
    const int b  = blockIdx.y;
    const int sp = blockIdx.x;
    const int wid = threadIdx.x >> 5, lane = threadIdx.x & 31;
    const int m0 = sp * (LM / NSPLIT);

    // phase 1: betas for 32 rows
#pragma unroll
    for (int rr = 0; rr < 4; rr++) {
        const int m = m0 + wid * 4 + rr;
        const float4* mp = (const float4*)(mainp + ((size_t)b * LM + m) * D);
        const float4* ap = (const float4*)(g_A   + ((size_t)b * LM + m) * D);
        float s = 0.f;
#pragma unroll
        for (int j = 0; j < 6; j++) {
            const int idx = lane + j * 32;         // float4 index within row (192 total)
            float4 mv = mp[idx], av = ap[idx];
            float4 w1 = ((const float4*)w)[idx];
            float4 w2 = ((const float4*)(w + D))[idx];
            s += (mv.x - av.x) * w1.x + (mv.x * av.x) * w2.x;
            s += (mv.y - av.y) * w1.y + (mv.y * av.y) * w2.y;
            s += (mv.z - av.z) * w1.z + (mv.z * av.z) * w2.z;
            s += (mv.w - av.w) * w1.w + (mv.w * av.w) * w2.w;
        }
#pragma unroll
        for (int o = 16; o; o >>= 1) s += __shfl_xor_sync(0xffffffffu, s, o);
        if (lane == 0) sbeta[wid * 4 + rr] = s;
    }
    __syncthreads();

    // phase 2: weighted pooling over the same 32 rows (L2-resident)
    float ss[3] = {0.f, 0.f, 0.f}, sm[3] = {0.f, 0.f, 0.f};
    for (int i = 0; i < 32; i++) {
        const float bt = sbeta[i];
        const float* mp = mainp + ((size_t)b * LM + m0 + i) * D;
        const float* ap = g_A   + ((size_t)b * LM + m0 + i) * D;
#pragma unroll
        for (int j = 0; j < 3; j++) {
            const int d = threadIdx.x + j * 256;
            float mv = mp[d], av = ap[d];
            ss[j] += bt * (mv - av);
            sm[j] += bt * (mv * av);
        }
    }
    float* pp = g_part + (size_t)(b * NSPLIT + sp) * 2 * D;
#pragma unroll
    for (int j = 0; j < 3; j++) {
        const int d = threadIdx.x + j * 256;
        pp[d]     = ss[j];
        pp[D + d] = sm[j];
    }
}

__global__ __launch_bounds__(256) void pooled_reduce(float* __restrict__ out)
{
    const int b = blockIdx.x;
    for (int k = threadIdx.x; k < 2 * D; k += 256) {
        float s = 0.f;
#pragma unroll
        for (int sp = 0; sp < NSPLIT; sp++)
            s += g_part[(size_t)(b * NSPLIT + sp) * 2 * D + k];
        out[(size_t)b * 2 * D + k] = s;
    }
}

// ---------------------------------------------------------------------------
extern "C" void kernel_launch(void* const* d_in, const int* in_sizes, int n_in,
                              void* d_out, int out_size)
{
    const float* mainp = (const float*)d_in[0];   // (B, LM, D)
    const float* xp    = (const float*)d_in[1];   // (B, LX, D)
    const float* Wp    = (const float*)d_in[2];   // (D, D)
    const float* wp    = (const float*)d_in[3];   // (2D, 1)
    float*       out   = (float*)d_out;           // (B, 2D)

    cudaFuncSetAttribute(gemm_bf16, cudaFuncAttributeMaxDynamicSharedMemorySize, GSMEM);

    unsigned short *xTh, *xTl, *Gh, *Gl, *Ph, *Pl, *mh, *ml, *Wh, *Wl;
    float *Aout;
    cudaGetSymbolAddress((void**)&xTh, g_xTh);
    cudaGetSymbolAddress((void**)&xTl, g_xTl);
    cudaGetSymbolAddress((void**)&Gh,  g_Gh);
    cudaGetSymbolAddress((void**)&Gl,  g_Gl);
    cudaGetSymbolAddress((void**)&Ph,  g_Ph);
    cudaGetSymbolAddress((void**)&Pl,  g_Pl);
    cudaGetSymbolAddress((void**)&mh,  g_mh);
    cudaGetSymbolAddress((void**)&ml,  g_ml);
    cudaGetSymbolAddress((void**)&Wh,  g_Wh);
    cudaGetSymbolAddress((void**)&Wl,  g_Wl);
    cudaGetSymbolAddress((void**)&Aout, g_A);

    // operand preparation (bf16 hi/lo)
    transpose_split_x<<<dim3(LX / 32, D / 32, B_SZ), dim3(32, 8)>>>(xp);
    split_kernel<<<(D * D / 4 + 255) / 256, 256>>>(Wp, Wh, Wl, D * D / 4);
    split_kernel<<<((int)((size_t)B_SZ * LM * D / 4) + 255) / 256, 256>>>(
        mainp, mh, ml, (int)((size_t)B_SZ * LM * D / 4));

    // 1) G_b = xT_b @ xT_b^T (symmetric: 21 upper blocks + mirror)
    gemm_bf16<<<dim3(21, 1, B_SZ), 256, GSMEM>>>(
        xTh, xTl, xTh, xTl, nullptr, Gh, Gl,
        D, LX, (long)D * LX, (long)D * LX, (long)D * D, 1, 1);
    mirror_G<<<dim3(16, 15, B_SZ), dim3(32, 8)>>>();

    // 2) P_b = G_b @ W^T     (D x D, K = D), W broadcast, split output
    gemm_bf16<<<dim3(D / 128, D / 128, B_SZ), 256, GSMEM>>>(
        Gh, Gl, Wh, Wl, nullptr, Ph, Pl,
        D, D, (long)D * D, 0L, (long)D * D, 1, 0);

    // 3) A_b = main_b @ P_b^T (LM x D, K = D), fp32 output
    gemm_bf16<<<dim3(D / 128, LM / 128, B_SZ), 256, GSMEM>>>(
        mh, ml, Ph, Pl, Aout, Ph, Pl,
        D, D, (long)LM * D, (long)D * D, (long)LM * D, 0, 0);

    // 4) fused beta + pooled partials, deterministic reduce
    beta_pooled_fused<<<dim3(NSPLIT, B_SZ), 256>>>(mainp, wp);
    pooled_reduce<<<B_SZ, 256>>>(out);
}

// round 14
// speedup vs baseline: 1.3707x; 1.1143x over previous
#include <cuda_runtime.h>
#include <cuda_bf16.h>
#include <cstdint>

#define B_SZ 16
#define LM   1024
#define LX   1024
#define D    768
#define NSPLIT 32

// ---------------- scratch (static; allocation-free) ----------------
__device__ unsigned short g_xTh[(size_t)B_SZ * D * LX];
__device__ unsigned short g_xTl[(size_t)B_SZ * D * LX];
__device__ unsigned short g_Gh [(size_t)B_SZ * D * D];
__device__ unsigned short g_Gl [(size_t)B_SZ * D * D];
__device__ unsigned short g_Ph [(size_t)B_SZ * D * D];
__device__ unsigned short g_Pl [(size_t)B_SZ * D * D];
__device__ unsigned short g_mh [(size_t)B_SZ * LM * D];
__device__ unsigned short g_ml [(size_t)B_SZ * LM * D];
__device__ unsigned short g_Wh [D * D];
__device__ unsigned short g_Wl [D * D];
__device__ float g_A   [(size_t)B_SZ * LM * D];
__device__ float g_part[B_SZ * NSPLIT * 2 * D];

// triangular block enumeration, 64-col x 128-row blocks: keep iff bx >= 2*by
__constant__ signed char c_trix[42] = {0,1,2,3,4,5,6,7,8,9,10,11,
                                       2,3,4,5,6,7,8,9,10,11,
                                       4,5,6,7,8,9,10,11,
                                       6,7,8,9,10,11,
                                       8,9,10,11,
                                       10,11};
__constant__ signed char c_triy[42] = {0,0,0,0,0,0,0,0,0,0,0,0,
                                       1,1,1,1,1,1,1,1,1,1,
                                       2,2,2,2,2,2,2,2,
                                       3,3,3,3,3,3,
                                       4,4,4,4,
                                       5,5};
// lower 128x128 blocks to mirror-fill (RB > CB)
__constant__ int c_mrb[15] = {1,2,2,3,3,3,4,4,4,4,5,5,5,5,5};
__constant__ int c_mcb[15] = {0,0,1,0,1,2,0,1,2,3,0,1,2,3,4};

// ---------------- helpers ----------------
__device__ __forceinline__ uint32_t smem_u32(const void* p) {
    uint32_t a;
    asm("{ .reg .u64 t; cvta.to.shared.u64 t, %1; cvt.u32.u64 %0, t; }" : "=r"(a) : "l"(p));
    return a;
}
__device__ __forceinline__ void cpa16(uint32_t dst, const void* src) {
    asm volatile("cp.async.cg.shared.global [%0], [%1], 16;" :: "r"(dst), "l"(src));
}
#define CP_COMMIT() asm volatile("cp.async.commit_group;" ::: "memory")
#define CP_WAIT(n)  asm volatile("cp.async.wait_group %0;" :: "n"(n) : "memory")

__device__ __forceinline__ void ldm4(uint32_t* r, uint32_t addr) {
    asm volatile("ldmatrix.sync.aligned.m8n8.x4.shared.b16 {%0,%1,%2,%3}, [%4];"
                 : "=r"(r[0]), "=r"(r[1]), "=r"(r[2]), "=r"(r[3]) : "r"(addr));
}
__device__ __forceinline__ void mma16816(float* d, const uint32_t* a, uint32_t b0, uint32_t b1) {
    asm volatile("mma.sync.aligned.m16n8k16.row.col.f32.bf16.bf16.f32 "
                 "{%0,%1,%2,%3}, {%4,%5,%6,%7}, {%8,%9}, {%0,%1,%2,%3};"
                 : "+f"(d[0]), "+f"(d[1]), "+f"(d[2]), "+f"(d[3])
                 : "r"(a[0]), "r"(a[1]), "r"(a[2]), "r"(a[3]), "r"(b0), "r"(b1));
}
__device__ __forceinline__ void split1(float v, unsigned short& h, unsigned short& l) {
    __nv_bfloat16 hb = __float2bfloat16(v);
    __nv_bfloat16 lb = __float2bfloat16(v - __bfloat162float(hb));
    h = __bfloat16_as_ushort(hb);
    l = __bfloat16_as_ushort(lb);
}
__device__ __forceinline__ uint32_t packus(unsigned short a, unsigned short b) {
    return ((uint32_t)b << 16) | (uint32_t)a;
}

// ---------------------------------------------------------------------------
// bf16 split-GEMM: C[M,N] = A*B^T, A = Ah+Al, B = Bh+Bl (bf16 hi/lo),
// fp32 accumulate via mma.sync m16n8k16. CTA tile 128x64, K-chunk 64,
// 2-stage cp.async pipeline, 96 KB smem -> 2 CTAs/SM.
// ---------------------------------------------------------------------------
#define A_TILE_B 16384               // 128 x 64 bf16
#define B_TILE_B 8192                // 64 x 64 bf16
#define STAGE_B  (2 * A_TILE_B + 2 * B_TILE_B)   // 48 KB
#define GSMEM    (2 * STAGE_B)                   // 96 KB

__global__ __launch_bounds__(256, 2) void gemm_bf16(
    const unsigned short* __restrict__ Ah, const unsigned short* __restrict__ Al,
    const unsigned short* __restrict__ Bh, const unsigned short* __restrict__ Bl,
    float* __restrict__ C, unsigned short* __restrict__ Ch, unsigned short* __restrict__ Cl,
    int N, int K, long sA, long sB, long sC, int split_out, int tri)
{
    extern __shared__ char smem[];
    const uint32_t sbt = smem_u32(smem);

    const int tid  = threadIdx.x;
    const int lane = tid & 31;
    const int wid  = tid >> 5;
    const int warp_m = wid & 3;        // 4 warps along M (32 rows each)
    const int warp_n = wid >> 2;       // 2 warps along N (32 cols each)
    int bx, by;
    if (tri) { bx = c_trix[blockIdx.x]; by = c_triy[blockIdx.x]; }
    else     { bx = blockIdx.x;         by = blockIdx.y; }
    const int brow = by * 128, bcol = bx * 64;
    const long bz = blockIdx.z;

    // per-tile sources and smem base offsets (tiles: 0=Ah, 1=Al, 2=Bh, 3=Bl)
    const unsigned short* tsrc[4] = {
        Ah + bz * sA + (size_t)brow * K,
        Al + bz * sA + (size_t)brow * K,
        Bh + bz * sB + (size_t)bcol * K,
        Bl + bz * sB + (size_t)bcol * K
    };
    const uint32_t tbo[4] = {0u, A_TILE_B, 2u * A_TILE_B, 2u * A_TILE_B + B_TILE_B};

    const int NC = K >> 6;

    // one cp.async (16B unit i of 12) for chunk c. un ranges are 256-aligned,
    // so tile selection resolves at compile time in the unrolled callers.
    auto issue_i = [&](int c, int i) {
        const int un = tid + i * 256;          // 0..3071
        int tileid, u;
        if      (un < 1024) { tileid = 0; u = un; }
        else if (un < 2048) { tileid = 1; u = un - 1024; }
        else if (un < 2560) { tileid = 2; u = un - 2048; }
        else                { tileid = 3; u = un - 2560; }
        const int row = u >> 3, q = u & 7;
        const uint32_t off = (uint32_t)((row * 8 + (q ^ (row & 7))) * 16);
        cpa16(sbt + (c & 1) * STAGE_B + tbo[tileid] + off,
              tsrc[tileid] + (size_t)row * K + c * 64 + q * 8);
    };

    float acc[2][4][4];
#pragma unroll
    for (int a = 0; a < 2; a++)
#pragma unroll
        for (int b = 0; b < 4; b++)
#pragma unroll
            for (int q = 0; q < 4; q++) acc[a][b][q] = 0.f;

    const int a_r    = lane & 15;
    const int a_kbit = lane >> 4;
    const int b_r    = (lane & 7) + ((lane >> 4) << 3);
    const int b_kbit = (lane >> 3) & 1;

#pragma unroll
    for (int i = 0; i < 12; i++) issue_i(0, i);
    CP_COMMIT();

    for (int c = 0; c < NC; c++) {
        CP_WAIT(0);
        __syncthreads();

        const uint32_t stg = sbt + (c & 1) * STAGE_B;
#pragma unroll
        for (int kk = 0; kk < 4; kk++) {
            if (c + 1 < NC) {
#pragma unroll
                for (int i = kk * 3; i < kk * 3 + 3; i++) issue_i(c + 1, i);
            }
            uint32_t ah[2][4], al[2][4], bh[2][4], bl[2][4];
#pragma unroll
            for (int mt = 0; mt < 2; mt++) {
                int row = warp_m * 32 + mt * 16 + a_r;
                int ku  = kk * 2 + a_kbit;
                uint32_t off = (uint32_t)((row * 8 + (ku ^ (row & 7))) * 16);
                ldm4(ah[mt], stg + off);
                ldm4(al[mt], stg + A_TILE_B + off);
            }
#pragma unroll
            for (int p = 0; p < 2; p++) {
                int row = warp_n * 32 + p * 16 + b_r;
                int ku  = kk * 2 + b_kbit;
                uint32_t off = (uint32_t)((row * 8 + (ku ^ (row & 7))) * 16);
                ldm4(bh[p], stg + 2 * A_TILE_B + off);
                ldm4(bl[p], stg + 2 * A_TILE_B + B_TILE_B + off);
            }
#pragma unroll
            for (int mt = 0; mt < 2; mt++)
#pragma unroll
                for (int nt = 0; nt < 4; nt++) {
                    const int p = nt >> 1, q = (nt & 1) * 2;
                    mma16816(acc[mt][nt], ah[mt], bh[p][q], bh[p][q + 1]);
                    mma16816(acc[mt][nt], al[mt], bh[p][q], bh[p][q + 1]);
                    mma16816(acc[mt][nt], ah[mt], bl[p][q], bl[p][q + 1]);
                }
        }
        if (c + 1 < NC) CP_COMMIT();
    }

    // epilogue
    float*          Cb  = C  ? C  + bz * sC : nullptr;
    unsigned short* Chb = Ch + bz * sC;
    unsigned short* Clb = Cl + bz * sC;
#pragma unroll
    for (int mt = 0; mt < 2; mt++)
#pragma unroll
        for (int nt = 0; nt < 4; nt++) {
            const float* dd = acc[mt][nt];
            const int r   = brow + warp_m * 32 + mt * 16 + (lane >> 2);
            const int col = bcol + warp_n * 32 + nt * 8 + (lane & 3) * 2;
            if (!split_out) {
                *(float2*)&Cb[(size_t)r * N + col]       = make_float2(dd[0], dd[1]);
                *(float2*)&Cb[(size_t)(r + 8) * N + col] = make_float2(dd[2], dd[3]);
            } else {
                unsigned short h0, l0, h1, l1;
                split1(dd[0], h0, l0); split1(dd[1], h1, l1);
                *(uint32_t*)&Chb[(size_t)r * N + col] = packus(h0, h1);
                *(uint32_t*)&Clb[(size_t)r * N + col] = packus(l0, l1);
                split1(dd[2], h0, l0); split1(dd[3], h1, l1);
                *(uint32_t*)&Chb[(size_t)(r + 8) * N + col] = packus(h0, h1);
                *(uint32_t*)&Clb[(size_t)(r + 8) * N + col] = packus(l0, l1);
            }
        }
}

// ---------------------------------------------------------------------------
// Fill lower-triangle blocks of G (RB > CB) from upper: G[r][c] = G[c][r]
// ---------------------------------------------------------------------------
__global__ __launch_bounds__(256) void mirror_G()
{
    __shared__ unsigned short th[32][33], tl[32][33];
    const int b = blockIdx.z;
    const int p = blockIdx.y;
    const int t = blockIdx.x;                 // 0..15: 4x4 subtiles of 128x128
    const int r0 = c_mrb[p] * 128 + (t >> 2) * 32;
    const int c0 = c_mcb[p] * 128 + (t & 3) * 32;
    const int tx = threadIdx.x, ty = threadIdx.y;
    unsigned short* Gh = g_Gh + (size_t)b * D * D;
    unsigned short* Gl = g_Gl + (size_t)b * D * D;
#pragma unroll
    for (int i = 0; i < 32; i += 8) {
        th[ty + i][tx] = Gh[(size_t)(c0 + ty + i) * D + r0 + tx];
        tl[ty + i][tx] = Gl[(size_t)(c0 + ty + i) * D + r0 + tx];
    }
    __syncthreads();
#pragma unroll
    for (int i = 0; i < 32; i += 8) {
        Gh[(size_t)(r0 + ty + i) * D + c0 + tx] = th[tx][ty + i];
        Gl[(size_t)(r0 + ty + i) * D + c0 + tx] = tl[tx][ty + i];
    }
}

// ---------------------------------------------------------------------------
// x [B,LX,D] fp32 -> xTh/xTl [B,D,LX] bf16 hi/lo (fused transpose + split)
// ---------------------------------------------------------------------------
__global__ __launch_bounds__(256) void transpose_split_x(const float* __restrict__ x)
{
    __shared__ float t[32][33];
    const int b = blockIdx.z;
    const int l0 = blockIdx.x * 32, d0 = blockIdx.y * 32;
    const int tx = threadIdx.x, ty = threadIdx.y;
    const float* xp = x + (size_t)b * LX * D;
#pragma unroll
    for (int i = 0; i < 32; i += 8)
        t[ty + i][tx] = xp[(size_t)(l0 + ty + i) * D + d0 + tx];
    __syncthreads();
#pragma unroll
    for (int i = 0; i < 32; i += 8) {
        float v = t[tx][ty + i];
        unsigned short h, l; split1(v, h, l);
        size_t o = ((size_t)b * D + d0 + ty + i) * LX + l0 + tx;
        g_xTh[o] = h;
        g_xTl[o] = l;
    }
}

// fp32 -> bf16 hi/lo split (vectorized)
__global__ __launch_bounds__(256) void split_kernel(
    const float* __restrict__ src, unsigned short* __restrict__ h,
    unsigned short* __restrict__ l, int n4)
{
    int i = blockIdx.x * 256 + threadIdx.x;
    if (i >= n4) return;
    float4 v = ((const float4*)src)[i];
    unsigned short h0, l0, h1, l1, h2, l2, h3, l3;
    split1(v.x, h0, l0); split1(v.y, h1, l1);
    split1(v.z, h2, l2); split1(v.w, h3, l3);
    ((uint2*)h)[i] = make_uint2(packus(h0, h1), packus(h2, h3));
    ((uint2*)l)[i] = make_uint2(packus(l0, l1), packus(l2, l3));
}

// ---------------------------------------------------------------------------
// Fused beta + pooled partials (proven R13 version).
// ---------------------------------------------------------------------------
__global__ __launch_bounds__(256) void beta_pooled_fused(
    const float* __restrict__ mainp, const float* __restrict__ w)
{
    __shared__ float sbeta[32];
    const int b  = blockIdx.y;
    const int sp = blockIdx.x;
    const int wid = threadIdx.x >> 5, lane = threadIdx.x & 31;
    const int m0 = sp * (LM / NSPLIT);

    // phase 1: betas for 32 rows
#pragma unroll
    for (int rr = 0; rr < 4; rr++) {
        const int m = m0 + wid * 4 + rr;
        const float4* mp = (const float4*)(mainp + ((size_t)b * LM + m) * D);
        const float4* ap = (const float4*)(g_A   + ((size_t)b * LM + m) * D);
        float s = 0.f;
#pragma unroll
        for (int j = 0; j < 6; j++) {
            const int idx = lane + j * 32;
            float4 mv = mp[idx], av = ap[idx];
            float4 w1 = ((const float4*)w)[idx];
            float4 w2 = ((const float4*)(w + D))[idx];
            s += (mv.x - av.x) * w1.x + (mv.x * av.x) * w2.x;
            s += (mv.y - av.y) * w1.y + (mv.y * av.y) * w2.y;
            s += (mv.z - av.z) * w1.z + (mv.z * av.z) * w2.z;
            s += (mv.w - av.w) * w1.w + (mv.w * av.w) * w2.w;
        }
#pragma unroll
        for (int o = 16; o; o >>= 1) s += __shfl_xor_sync(0xffffffffu, s, o);
        if (lane == 0) sbeta[wid * 4 + rr] = s;
    }
    __syncthreads();

    // phase 2: weighted pooling over the same 32 rows (L2-resident)
    float ss[3] = {0.f, 0.f, 0.f}, sm[3] = {0.f, 0.f, 0.f};
    for (int i = 0; i < 32; i++) {
        const float bt = sbeta[i];
        const float* mp = mainp + ((size_t)b * LM + m0 + i) * D;
        const float* ap = g_A   + ((size_t)b * LM + m0 + i) * D;
#pragma unroll
        for (int j = 0; j < 3; j++) {
            const int d = threadIdx.x + j * 256;
            float mv = mp[d], av = ap[d];
            ss[j] += bt * (mv - av);
            sm[j] += bt * (mv * av);
        }
    }
    float* pp = g_part + (size_t)(b * NSPLIT + sp) * 2 * D;
#pragma unroll
    for (int j = 0; j < 3; j++) {
        const int d = threadIdx.x + j * 256;
        pp[d]     = ss[j];
        pp[D + d] = sm[j];
    }
}

__global__ __launch_bounds__(256) void pooled_reduce(float* __restrict__ out)
{
    const int b = blockIdx.x;
    for (int k = threadIdx.x; k < 2 * D; k += 256) {
        float s = 0.f;
#pragma unroll
        for (int sp = 0; sp < NSPLIT; sp++)
            s += g_part[(size_t)(b * NSPLIT + sp) * 2 * D + k];
        out[(size_t)b * 2 * D + k] = s;
    }
}

// ---------------------------------------------------------------------------
extern "C" void kernel_launch(void* const* d_in, const int* in_sizes, int n_in,
                              void* d_out, int out_size)
{
    const float* mainp = (const float*)d_in[0];   // (B, LM, D)
    const float* xp    = (const float*)d_in[1];   // (B, LX, D)
    const float* Wp    = (const float*)d_in[2];   // (D, D)
    const float* wp    = (const float*)d_in[3];   // (2D, 1)
    float*       out   = (float*)d_out;           // (B, 2D)

    cudaFuncSetAttribute(gemm_bf16, cudaFuncAttributeMaxDynamicSharedMemorySize, GSMEM);

    unsigned short *xTh, *xTl, *Gh, *Gl, *Ph, *Pl, *mh, *ml, *Wh, *Wl;
    float *Aout;
    cudaGetSymbolAddress((void**)&xTh, g_xTh);
    cudaGetSymbolAddress((void**)&xTl, g_xTl);
    cudaGetSymbolAddress((void**)&Gh,  g_Gh);
    cudaGetSymbolAddress((void**)&Gl,  g_Gl);
    cudaGetSymbolAddress((void**)&Ph,  g_Ph);
    cudaGetSymbolAddress((void**)&Pl,  g_Pl);
    cudaGetSymbolAddress((void**)&mh,  g_mh);
    cudaGetSymbolAddress((void**)&ml,  g_ml);
    cudaGetSymbolAddress((void**)&Wh,  g_Wh);
    cudaGetSymbolAddress((void**)&Wl,  g_Wl);
    cudaGetSymbolAddress((void**)&Aout, g_A);

    // operand preparation (bf16 hi/lo)
    transpose_split_x<<<dim3(LX / 32, D / 32, B_SZ), dim3(32, 8)>>>(xp);
    split_kernel<<<(D * D / 4 + 255) / 256, 256>>>(Wp, Wh, Wl, D * D / 4);
    split_kernel<<<((int)((size_t)B_SZ * LM * D / 4) + 255) / 256, 256>>>(
        mainp, mh, ml, (int)((size_t)B_SZ * LM * D / 4));

    // 1) G_b = xT_b @ xT_b^T (symmetric: 42 upper 64-col blocks + mirror)
    gemm_bf16<<<dim3(42, 1, B_SZ), 256, GSMEM>>>(
        xTh, xTl, xTh, xTl, nullptr, Gh, Gl,
        D, LX, (long)D * LX, (long)D * LX, (long)D * D, 1, 1);
    mirror_G<<<dim3(16, 15, B_SZ), dim3(32, 8)>>>();

    // 2) P_b = G_b @ W^T     (D x D, K = D), W broadcast, split output
    gemm_bf16<<<dim3(D / 64, D / 128, B_SZ), 256, GSMEM>>>(
        Gh, Gl, Wh, Wl, nullptr, Ph, Pl,
        D, D, (long)D * D, 0L, (long)D * D, 1, 0);

    // 3) A_b = main_b @ P_b^T (LM x D, K = D), fp32 output
    gemm_bf16<<<dim3(D / 64, LM / 128, B_SZ), 256, GSMEM>>>(
        mh, ml, Ph, Pl, Aout, Ph, Pl,
        D, D, (long)LM * D, (long)D * D, (long)LM * D, 0, 0);

    // 4) fused beta + pooled partials, deterministic reduce
    beta_pooled_fused<<<dim3(NSPLIT, B_SZ), 256>>>(mainp, wp);
    pooled_reduce<<<B_SZ, 256>>>(out);
}

// round 15
// speedup vs baseline: 1.3930x; 1.0163x over previous
#include <cuda_runtime.h>
#include <cuda_bf16.h>
#include <cstdint>

#define B_SZ 16
#define LM   1024
#define LX   1024
#define D    768
#define NSPLIT 32

// ---------------- scratch (static; allocation-free) ----------------
__device__ unsigned short g_xTh[(size_t)B_SZ * D * LX];
__device__ unsigned short g_xTl[(size_t)B_SZ * D * LX];
__device__ unsigned short g_Gh [(size_t)B_SZ * D * D];
__device__ unsigned short g_Gl [(size_t)B_SZ * D * D];
__device__ unsigned short g_Ph [(size_t)B_SZ * D * D];
__device__ unsigned short g_Pl [(size_t)B_SZ * D * D];
__device__ unsigned short g_mh [(size_t)B_SZ * LM * D];
__device__ unsigned short g_ml [(size_t)B_SZ * LM * D];
__device__ unsigned short g_Wh [D * D];
__device__ unsigned short g_Wl [D * D];
__device__ float g_A   [(size_t)B_SZ * LM * D];
__device__ float g_part[B_SZ * NSPLIT * 2 * D];

// triangular block enumeration, 64-col x 128-row blocks: keep iff bx >= 2*by
__constant__ signed char c_trix[42] = {0,1,2,3,4,5,6,7,8,9,10,11,
                                       2,3,4,5,6,7,8,9,10,11,
                                       4,5,6,7,8,9,10,11,
                                       6,7,8,9,10,11,
                                       8,9,10,11,
                                       10,11};
__constant__ signed char c_triy[42] = {0,0,0,0,0,0,0,0,0,0,0,0,
                                       1,1,1,1,1,1,1,1,1,1,
                                       2,2,2,2,2,2,2,2,
                                       3,3,3,3,3,3,
                                       4,4,4,4,
                                       5,5};

// ---------------- helpers ----------------
__device__ __forceinline__ uint32_t smem_u32(const void* p) {
    uint32_t a;
    asm("{ .reg .u64 t; cvta.to.shared.u64 t, %1; cvt.u32.u64 %0, t; }" : "=r"(a) : "l"(p));
    return a;
}
__device__ __forceinline__ void cpa16(uint32_t dst, const void* src) {
    asm volatile("cp.async.cg.shared.global [%0], [%1], 16;" :: "r"(dst), "l"(src));
}
#define CP_COMMIT() asm volatile("cp.async.commit_group;" ::: "memory")
#define CP_WAIT(n)  asm volatile("cp.async.wait_group %0;" :: "n"(n) : "memory")

__device__ __forceinline__ void ldm4(uint32_t* r, uint32_t addr) {
    asm volatile("ldmatrix.sync.aligned.m8n8.x4.shared.b16 {%0,%1,%2,%3}, [%4];"
                 : "=r"(r[0]), "=r"(r[1]), "=r"(r[2]), "=r"(r[3]) : "r"(addr));
}
__device__ __forceinline__ void mma16816(float* d, const uint32_t* a, uint32_t b0, uint32_t b1) {
    asm volatile("mma.sync.aligned.m16n8k16.row.col.f32.bf16.bf16.f32 "
                 "{%0,%1,%2,%3}, {%4,%5,%6,%7}, {%8,%9}, {%0,%1,%2,%3};"
                 : "+f"(d[0]), "+f"(d[1]), "+f"(d[2]), "+f"(d[3])
                 : "r"(a[0]), "r"(a[1]), "r"(a[2]), "r"(a[3]), "r"(b0), "r"(b1));
}
__device__ __forceinline__ void split1(float v, unsigned short& h, unsigned short& l) {
    __nv_bfloat16 hb = __float2bfloat16(v);
    __nv_bfloat16 lb = __float2bfloat16(v - __bfloat162float(hb));
    h = __bfloat16_as_ushort(hb);
    l = __bfloat16_as_ushort(lb);
}
__device__ __forceinline__ uint32_t packus(unsigned short a, unsigned short b) {
    return ((uint32_t)b << 16) | (uint32_t)a;
}

// ---------------------------------------------------------------------------
// bf16 split-GEMM: C[M,N] = A*B^T, A = Ah+Al, B = Bh+Bl (bf16 hi/lo),
// fp32 accumulate via mma.sync m16n8k16. CTA tile 128x64, K-chunk 64,
// 2-stage cp.async pipeline, 96 KB smem -> 2 CTAs/SM.
// tri mode: triangular grid; strictly-upper tiles also write their
// transpose to C's lower triangle (fused mirror) via stage smem.
// ---------------------------------------------------------------------------
#define A_TILE_B 16384               // 128 x 64 bf16
#define B_TILE_B 8192                // 64 x 64 bf16
#define STAGE_B  (2 * A_TILE_B + 2 * B_TILE_B)   // 48 KB
#define GSMEM    (2 * STAGE_B)                   // 96 KB

__global__ __launch_bounds__(256, 2) void gemm_bf16(
    const unsigned short* __restrict__ Ah, const unsigned short* __restrict__ Al,
    const unsigned short* __restrict__ Bh, const unsigned short* __restrict__ Bl,
    float* __restrict__ C, unsigned short* __restrict__ Ch, unsigned short* __restrict__ Cl,
    int N, int K, long sA, long sB, long sC, int split_out, int tri)
{
    extern __shared__ char smem[];
    const uint32_t sbt = smem_u32(smem);

    const int tid  = threadIdx.x;
    const int lane = tid & 31;
    const int wid  = tid >> 5;
    const int warp_m = wid & 3;        // 4 warps along M (32 rows each)
    const int warp_n = wid >> 2;       // 2 warps along N (32 cols each)
    int bx, by;
    if (tri) { bx = c_trix[blockIdx.x]; by = c_triy[blockIdx.x]; }
    else     { bx = blockIdx.x;         by = blockIdx.y; }
    const int brow = by * 128, bcol = bx * 64;
    const long bz = blockIdx.z;
    const int do_mirror = tri && (bx >= 2 * by + 2);

    // per-tile sources and smem base offsets (tiles: 0=Ah, 1=Al, 2=Bh, 3=Bl)
    const unsigned short* tsrc[4] = {
        Ah + bz * sA + (size_t)brow * K,
        Al + bz * sA + (size_t)brow * K,
        Bh + bz * sB + (size_t)bcol * K,
        Bl + bz * sB + (size_t)bcol * K
    };
    const uint32_t tbo[4] = {0u, A_TILE_B, 2u * A_TILE_B, 2u * A_TILE_B + B_TILE_B};

    const int NC = K >> 6;

    auto issue_i = [&](int c, int i) {
        const int un = tid + i * 256;          // 0..3071
        int tileid, u;
        if      (un < 1024) { tileid = 0; u = un; }
        else if (un < 2048) { tileid = 1; u = un - 1024; }
        else if (un < 2560) { tileid = 2; u = un - 2048; }
        else                { tileid = 3; u = un - 2560; }
        const int row = u >> 3, q = u & 7;
        const uint32_t off = (uint32_t)((row * 8 + (q ^ (row & 7))) * 16);
        cpa16(sbt + (c & 1) * STAGE_B + tbo[tileid] + off,
              tsrc[tileid] + (size_t)row * K + c * 64 + q * 8);
    };

    float acc[2][4][4];
#pragma unroll
    for (int a = 0; a < 2; a++)
#pragma unroll
        for (int b = 0; b < 4; b++)
#pragma unroll
            for (int q = 0; q < 4; q++) acc[a][b][q] = 0.f;

    const int a_r    = lane & 15;
    const int a_kbit = lane >> 4;
    const int b_r    = (lane & 7) + ((lane >> 4) << 3);
    const int b_kbit = (lane >> 3) & 1;

#pragma unroll
    for (int i = 0; i < 12; i++) issue_i(0, i);
    CP_COMMIT();

    for (int c = 0; c < NC; c++) {
        CP_WAIT(0);
        __syncthreads();

        const uint32_t stg = sbt + (c & 1) * STAGE_B;
#pragma unroll
        for (int kk = 0; kk < 4; kk++) {
            if (c + 1 < NC) {
#pragma unroll
                for (int i = kk * 3; i < kk * 3 + 3; i++) issue_i(c + 1, i);
            }
            uint32_t ah[2][4], al[2][4], bh[2][4], bl[2][4];
#pragma unroll
            for (int mt = 0; mt < 2; mt++) {
                int row = warp_m * 32 + mt * 16 + a_r;
                int ku  = kk * 2 + a_kbit;
                uint32_t off = (uint32_t)((row * 8 + (ku ^ (row & 7))) * 16);
                ldm4(ah[mt], stg + off);
                ldm4(al[mt], stg + A_TILE_B + off);
            }
#pragma unroll
            for (int p = 0; p < 2; p++) {
                int row = warp_n * 32 + p * 16 + b_r;
                int ku  = kk * 2 + b_kbit;
                uint32_t off = (uint32_t)((row * 8 + (ku ^ (row & 7))) * 16);
                ldm4(bh[p], stg + 2 * A_TILE_B + off);
                ldm4(bl[p], stg + 2 * A_TILE_B + B_TILE_B + off);
            }
#pragma unroll
            for (int mt = 0; mt < 2; mt++)
#pragma unroll
                for (int nt = 0; nt < 4; nt++) {
                    const int p = nt >> 1, q = (nt & 1) * 2;
                    mma16816(acc[mt][nt], ah[mt], bh[p][q], bh[p][q + 1]);
                    mma16816(acc[mt][nt], al[mt], bh[p][q], bh[p][q + 1]);
                    mma16816(acc[mt][nt], ah[mt], bl[p][q], bl[p][q + 1]);
                }
        }
        if (c + 1 < NC) CP_COMMIT();
    }

    // mirror staging buffers (reuse stage smem after mainloop):
    // s_h/s_l: [64 cols][130 ushorts] (128 rows + 2 pad) per array
    unsigned short* s_h = (unsigned short*)smem;
    unsigned short* s_l = s_h + 64 * 130;
    if (do_mirror) __syncthreads();   // all ldmatrix reads of stage smem done

    // epilogue
    float*          Cb  = C  ? C  + bz * sC : nullptr;
    unsigned short* Chb = Ch + bz * sC;
    unsigned short* Clb = Cl + bz * sC;
#pragma unroll
    for (int mt = 0; mt < 2; mt++)
#pragma unroll
        for (int nt = 0; nt < 4; nt++) {
            const float* dd = acc[mt][nt];
            const int rl  = warp_m * 32 + mt * 16 + (lane >> 2);
            const int cl0 = warp_n * 32 + nt * 8 + (lane & 3) * 2;
            const int r   = brow + rl;
            const int col = bcol + cl0;
            if (!split_out) {
                *(float2*)&Cb[(size_t)r * N + col]       = make_float2(dd[0], dd[1]);
                *(float2*)&Cb[(size_t)(r + 8) * N + col] = make_float2(dd[2], dd[3]);
            } else {
                unsigned short h0, l0, h1, l1;
                split1(dd[0], h0, l0); split1(dd[1], h1, l1);
                *(uint32_t*)&Chb[(size_t)r * N + col] = packus(h0, h1);
                *(uint32_t*)&Clb[(size_t)r * N + col] = packus(l0, l1);
                if (do_mirror) {
                    s_h[cl0 * 130 + rl] = h0; s_h[(cl0 + 1) * 130 + rl] = h1;
                    s_l[cl0 * 130 + rl] = l0; s_l[(cl0 + 1) * 130 + rl] = l1;
                }
                split1(dd[2], h0, l0); split1(dd[3], h1, l1);
                *(uint32_t*)&Chb[(size_t)(r + 8) * N + col] = packus(h0, h1);
                *(uint32_t*)&Clb[(size_t)(r + 8) * N + col] = packus(l0, l1);
                if (do_mirror) {
                    s_h[cl0 * 130 + rl + 8] = h0; s_h[(cl0 + 1) * 130 + rl + 8] = h1;
                    s_l[cl0 * 130 + rl + 8] = l0; s_l[(cl0 + 1) * 130 + rl + 8] = l1;
                }
            }
        }

    if (do_mirror) {
        __syncthreads();
        const uint32_t* su = (const uint32_t*)smem;   // 65 uints per 130-ushort row
#pragma unroll
        for (int i = 0; i < 16; i++) {
            const int idx = tid + i * 256;            // 0..4095
            const int cl  = idx >> 6;                 // 0..63   (output row' = bcol+cl)
            const int k   = idx & 63;                 // uint along rows (2 per uint)
            const uint32_t vh = su[cl * 65 + k];
            const uint32_t vl = su[64 * 65 + cl * 65 + k];
            *(uint32_t*)&Chb[(size_t)(bcol + cl) * N + brow + 2 * k] = vh;
            *(uint32_t*)&Clb[(size_t)(bcol + cl) * N + brow + 2 * k] = vl;
        }
    }
}

// ---------------------------------------------------------------------------
// x [B,LX,D] fp32 -> xTh/xTl [B,D,LX] bf16 hi/lo (fused transpose + split,
// packed uint32 stores; tile 64(l) x 32(d))
// ---------------------------------------------------------------------------
__global__ __launch_bounds__(256) void transpose_split_x(const float* __restrict__ x)
{
    __shared__ float t[64][33];
    const int b = blockIdx.z;
    const int lb = blockIdx.x * 64, d0 = blockIdx.y * 32;
    const int tx = threadIdx.x, ty = threadIdx.y;   // (32, 8)
    const float* xp = x + (size_t)b * LX * D;
#pragma unroll
    for (int i = 0; i < 64; i += 8)
        t[ty + i][tx] = xp[(size_t)(lb + ty + i) * D + d0 + tx];
    __syncthreads();
    const int tid = ty * 32 + tx;
#pragma unroll
    for (int i = 0; i < 4; i++) {
        const int s = tid + i * 256;        // 0..1023
        const int dd = s >> 5, lu = s & 31; // dd 0..31, lu 0..31 (pair index)
        float v0 = t[2 * lu][dd], v1 = t[2 * lu + 1][dd];
        unsigned short h0, lo0, h1, lo1;
        split1(v0, h0, lo0); split1(v1, h1, lo1);
        size_t o = ((size_t)b * D + d0 + dd) * LX + lb + 2 * lu;   // even
        *(uint32_t*)&g_xTh[o] = packus(h0, h1);
        *(uint32_t*)&g_xTl[o] = packus(lo0, lo1);
    }
}

// fp32 -> bf16 hi/lo split (vectorized)
__global__ __launch_bounds__(256) void split_kernel(
    const float* __restrict__ src, unsigned short* __restrict__ h,
    unsigned short* __restrict__ l, int n4)
{
    int i = blockIdx.x * 256 + threadIdx.x;
    if (i >= n4) return;
    float4 v = ((const float4*)src)[i];
    unsigned short h0, l0, h1, l1, h2, l2, h3, l3;
    split1(v.x, h0, l0); split1(v.y, h1, l1);
    split1(v.z, h2, l2); split1(v.w, h3, l3);
    ((uint2*)h)[i] = make_uint2(packus(h0, h1), packus(h2, h3));
    ((uint2*)l)[i] = make_uint2(packus(l0, l1), packus(l2, l3));
}

// ---------------------------------------------------------------------------
// Fused beta + pooled partials (proven R13 version).
// ---------------------------------------------------------------------------
__global__ __launch_bounds__(256) void beta_pooled_fused(
    const float* __restrict__ mainp, const float* __restrict__ w)
{
    __shared__ float sbeta[32];
    const int b  = blockIdx.y;
    const int sp = blockIdx.x;
    const int wid = threadIdx.x >> 5, lane = threadIdx.x & 31;
    const int m0 = sp * (LM / NSPLIT);

    // phase 1: betas for 32 rows
#pragma unroll
    for (int rr = 0; rr < 4; rr++) {
        const int m = m0 + wid * 4 + rr;
        const float4* mp = (const float4*)(mainp + ((size_t)b * LM + m) * D);
        const float4* ap = (const float4*)(g_A   + ((size_t)b * LM + m) * D);
        float s = 0.f;
#pragma unroll
        for (int j = 0; j < 6; j++) {
            const int idx = lane + j * 32;
            float4 mv = mp[idx], av = ap[idx];
            float4 w1 = ((const float4*)w)[idx];
            float4 w2 = ((const float4*)(w + D))[idx];
            s += (mv.x - av.x) * w1.x + (mv.x * av.x) * w2.x;
            s += (mv.y - av.y) * w1.y + (mv.y * av.y) * w2.y;
            s += (mv.z - av.z) * w1.z + (mv.z * av.z) * w2.z;
            s += (mv.w - av.w) * w1.w + (mv.w * av.w) * w2.w;
        }
#pragma unroll
        for (int o = 16; o; o >>= 1) s += __shfl_xor_sync(0xffffffffu, s, o);
        if (lane == 0) sbeta[wid * 4 + rr] = s;
    }
    __syncthreads();

    // phase 2: weighted pooling over the same 32 rows (L2-resident)
    float ss[3] = {0.f, 0.f, 0.f}, sm[3] = {0.f, 0.f, 0.f};
    for (int i = 0; i < 32; i++) {
        const float bt = sbeta[i];
        const float* mp = mainp + ((size_t)b * LM + m0 + i) * D;
        const float* ap = g_A   + ((size_t)b * LM + m0 + i) * D;
#pragma unroll
        for (int j = 0; j < 3; j++) {
            const int d = threadIdx.x + j * 256;
            float mv = mp[d], av = ap[d];
            ss[j] += bt * (mv - av);
            sm[j] += bt * (mv * av);
        }
    }
    float* pp = g_part + (size_t)(b * NSPLIT + sp) * 2 * D;
#pragma unroll
    for (int j = 0; j < 3; j++) {
        const int d = threadIdx.x + j * 256;
        pp[d]     = ss[j];
        pp[D + d] = sm[j];
    }
}

__global__ __launch_bounds__(256) void pooled_reduce(float* __restrict__ out)
{
    const int b = blockIdx.x;
    for (int k = threadIdx.x; k < 2 * D; k += 256) {
        float s = 0.f;
#pragma unroll
        for (int sp = 0; sp < NSPLIT; sp++)
            s += g_part[(size_t)(b * NSPLIT + sp) * 2 * D + k];
        out[(size_t)b * 2 * D + k] = s;
    }
}

// ---------------------------------------------------------------------------
extern "C" void kernel_launch(void* const* d_in, const int* in_sizes, int n_in,
                              void* d_out, int out_size)
{
    const float* mainp = (const float*)d_in[0];   // (B, LM, D)
    const float* xp    = (const float*)d_in[1];   // (B, LX, D)
    const float* Wp    = (const float*)d_in[2];   // (D, D)
    const float* wp    = (const float*)d_in[3];   // (2D, 1)
    float*       out   = (float*)d_out;           // (B, 2D)

    cudaFuncSetAttribute(gemm_bf16, cudaFuncAttributeMaxDynamicSharedMemorySize, GSMEM);

    unsigned short *xTh, *xTl, *Gh, *Gl, *Ph, *Pl, *mh, *ml, *Wh, *Wl;
    float *Aout;
    cudaGetSymbolAddress((void**)&xTh, g_xTh);
    cudaGetSymbolAddress((void**)&xTl, g_xTl);
    cudaGetSymbolAddress((void**)&Gh,  g_Gh);
    cudaGetSymbolAddress((void**)&Gl,  g_Gl);
    cudaGetSymbolAddress((void**)&Ph,  g_Ph);
    cudaGetSymbolAddress((void**)&Pl,  g_Pl);
    cudaGetSymbolAddress((void**)&mh,  g_mh);
    cudaGetSymbolAddress((void**)&ml,  g_ml);
    cudaGetSymbolAddress((void**)&Wh,  g_Wh);
    cudaGetSymbolAddress((void**)&Wl,  g_Wl);
    cudaGetSymbolAddress((void**)&Aout, g_A);

    // operand preparation (bf16 hi/lo)
    transpose_split_x<<<dim3(LX / 64, D / 32, B_SZ), dim3(32, 8)>>>(xp);
    split_kernel<<<(D * D / 4 + 255) / 256, 256>>>(Wp, Wh, Wl, D * D / 4);
    split_kernel<<<((int)((size_t)B_SZ * LM * D / 4) + 255) / 256, 256>>>(
        mainp, mh, ml, (int)((size_t)B_SZ * LM * D / 4));

    // 1) G_b = xT_b @ xT_b^T (symmetric: 42 upper 64-col blocks, fused mirror)
    gemm_bf16<<<dim3(42, 1, B_SZ), 256, GSMEM>>>(
        xTh, xTl, xTh, xTl, nullptr, Gh, Gl,
        D, LX, (long)D * LX, (long)D * LX, (long)D * D, 1, 1);

    // 2) P_b = G_b @ W^T     (D x D, K = D), W broadcast, split output
    gemm_bf16<<<dim3(D / 64, D / 128, B_SZ), 256, GSMEM>>>(
        Gh, Gl, Wh, Wl, nullptr, Ph, Pl,
        D, D, (long)D * D, 0L, (long)D * D, 1, 0);

    // 3) A_b = main_b @ P_b^T (LM x D, K = D), fp32 output
    gemm_bf16<<<dim3(D / 64, LM / 128, B_SZ), 256, GSMEM>>>(
        mh, ml, Ph, Pl, Aout, Ph, Pl,
        D, D, (long)LM * D, (long)D * D, (long)LM * D, 0, 0);

    // 4) fused beta + pooled partials, deterministic reduce
    beta_pooled_fused<<<dim3(NSPLIT, B_SZ), 256>>>(mainp, wp);
    pooled_reduce<<<B_SZ, 256>>>(out);
}

// round 17
// speedup vs baseline: 1.4291x; 1.0259x over previous
#include <cuda_runtime.h>
#include <cuda_bf16.h>
#include <cstdint>

#define B_SZ 16
#define LM   1024
#define LX   1024
#define D    768
#define NSPLIT 32
#define TRI_N 42
#define XTRA  14

// ---------------- scratch (static; allocation-free) ----------------
__device__ unsigned short g_xTh[(size_t)B_SZ * D * LX];
__device__ unsigned short g_xTl[(size_t)B_SZ * D * LX];
__device__ unsigned short g_Gh [(size_t)B_SZ * D * D];
__device__ unsigned short g_Gl [(size_t)B_SZ * D * D];
__device__ unsigned short g_Ph [(size_t)B_SZ * D * D];
__device__ unsigned short g_Pl [(size_t)B_SZ * D * D];
__device__ unsigned short g_mh [(size_t)B_SZ * LM * D];
__device__ unsigned short g_ml [(size_t)B_SZ * LM * D];
__device__ unsigned short g_Wh [D * D];
__device__ unsigned short g_Wl [D * D];
__device__ float g_A   [(size_t)B_SZ * LM * D];
__device__ float g_part[B_SZ * NSPLIT * 2 * D];

// triangular block enumeration, 64-col x 128-row blocks: keep iff bx >= 2*by
__constant__ signed char c_trix[42] = {0,1,2,3,4,5,6,7,8,9,10,11,
                                       2,3,4,5,6,7,8,9,10,11,
                                       4,5,6,7,8,9,10,11,
                                       6,7,8,9,10,11,
                                       8,9,10,11,
                                       10,11};
__constant__ signed char c_triy[42] = {0,0,0,0,0,0,0,0,0,0,0,0,
                                       1,1,1,1,1,1,1,1,1,1,
                                       2,2,2,2,2,2,2,2,
                                       3,3,3,3,3,3,
                                       4,4,4,4,
                                       5,5};

// ---------------- helpers ----------------
__device__ __forceinline__ uint32_t smem_u32(const void* p) {
    uint32_t a;
    asm("{ .reg .u64 t; cvta.to.shared.u64 t, %1; cvt.u32.u64 %0, t; }" : "=r"(a) : "l"(p));
    return a;
}
__device__ __forceinline__ void cpa16(uint32_t dst, const void* src) {
    asm volatile("cp.async.cg.shared.global [%0], [%1], 16;" :: "r"(dst), "l"(src));
}
#define CP_COMMIT() asm volatile("cp.async.commit_group;" ::: "memory")
#define CP_WAIT(n)  asm volatile("cp.async.wait_group %0;" :: "n"(n) : "memory")

__device__ __forceinline__ void ldm4(uint32_t* r, uint32_t addr) {
    asm volatile("ldmatrix.sync.aligned.m8n8.x4.shared.b16 {%0,%1,%2,%3}, [%4];"
                 : "=r"(r[0]), "=r"(r[1]), "=r"(r[2]), "=r"(r[3]) : "r"(addr));
}
__device__ __forceinline__ void mma16816(float* d, const uint32_t* a, uint32_t b0, uint32_t b1) {
    asm volatile("mma.sync.aligned.m16n8k16.row.col.f32.bf16.bf16.f32 "
                 "{%0,%1,%2,%3}, {%4,%5,%6,%7}, {%8,%9}, {%0,%1,%2,%3};"
                 : "+f"(d[0]), "+f"(d[1]), "+f"(d[2]), "+f"(d[3])
                 : "r"(a[0]), "r"(a[1]), "r"(a[2]), "r"(a[3]), "r"(b0), "r"(b1));
}
__device__ __forceinline__ void split1(float v, unsigned short& h, unsigned short& l) {
    __nv_bfloat16 hb = __float2bfloat16(v);
    __nv_bfloat16 lb = __float2bfloat16(v - __bfloat162float(hb));
    h = __bfloat16_as_ushort(hb);
    l = __bfloat16_as_ushort(lb);
}
__device__ __forceinline__ uint32_t packus(unsigned short a, unsigned short b) {
    return ((uint32_t)b << 16) | (uint32_t)a;
}

// ---------------------------------------------------------------------------
// bf16 split-GEMM: C[M,N] = A*B^T, A = Ah+Al, B = Bh+Bl (bf16 hi/lo),
// fp32 accumulate via mma.sync m16n8k16. CTA tile 128x64, K-chunk 64,
// 2-stage cp.async pipeline, 96 KB smem -> 2 CTAs/SM.
// tri mode: triangular grid; strictly-upper tiles also write their
// transpose to C's lower triangle (fused mirror) via stage smem.
// tri mode extra CTAs (blockIdx.x >= TRI_N): fp32->bf16 hi/lo splitter
// for main and W, soaking the idle tail-wave slots.
// ---------------------------------------------------------------------------
#define A_TILE_B 16384               // 128 x 64 bf16
#define B_TILE_B 8192                // 64 x 64 bf16
#define STAGE_B  (2 * A_TILE_B + 2 * B_TILE_B)   // 48 KB
#define GSMEM    (2 * STAGE_B)                   // 96 KB

__global__ __launch_bounds__(256, 2) void gemm_bf16(
    const unsigned short* __restrict__ Ah, const unsigned short* __restrict__ Al,
    const unsigned short* __restrict__ Bh, const unsigned short* __restrict__ Bl,
    float* __restrict__ C, unsigned short* __restrict__ Ch, unsigned short* __restrict__ Cl,
    int N, int K, long sA, long sB, long sC, int split_out, int tri,
    const float* __restrict__ spl_src, unsigned short* __restrict__ spl_h,
    unsigned short* __restrict__ spl_l, long spl_n4,
    const float* __restrict__ wsrc, unsigned short* __restrict__ wh,
    unsigned short* __restrict__ wl, int wn4)
{
    extern __shared__ char smem[];
    const uint32_t sbt = smem_u32(smem);

    const int tid  = threadIdx.x;

    // ---- splitter CTAs (tri mode, extra blockIdx.x slots) ----
    if (tri && blockIdx.x >= TRI_N) {
        const int e = (blockIdx.x - TRI_N) + XTRA * blockIdx.z;   // 0..223
        const long stride = (long)XTRA * B_SZ * 256;              // 57344
        for (long i = (long)e * 256 + tid; i < spl_n4; i += stride) {
            float4 v = ((const float4*)spl_src)[i];
            unsigned short h0, l0, h1, l1, h2, l2, h3, l3;
            split1(v.x, h0, l0); split1(v.y, h1, l1);
            split1(v.z, h2, l2); split1(v.w, h3, l3);
            ((uint2*)spl_h)[i] = make_uint2(packus(h0, h1), packus(h2, h3));
            ((uint2*)spl_l)[i] = make_uint2(packus(l0, l1), packus(l2, l3));
        }
        for (long i = (long)e * 256 + tid; i < wn4; i += stride) {
            float4 v = ((const float4*)wsrc)[i];
            unsigned short h0, l0, h1, l1, h2, l2, h3, l3;
            split1(v.x, h0, l0); split1(v.y, h1, l1);
            split1(v.z, h2, l2); split1(v.w, h3, l3);
            ((uint2*)wh)[i] = make_uint2(packus(h0, h1), packus(h2, h3));
            ((uint2*)wl)[i] = make_uint2(packus(l0, l1), packus(l2, l3));
        }
        return;
    }

    const int lane = tid & 31;
    const int wid  = tid >> 5;
    const int warp_m = wid & 3;        // 4 warps along M (32 rows each)
    const int warp_n = wid >> 2;       // 2 warps along N (32 cols each)
    int bx, by;
    if (tri) { bx = c_trix[blockIdx.x]; by = c_triy[blockIdx.x]; }
    else     { bx = blockIdx.x;         by = blockIdx.y; }
    const int brow = by * 128, bcol = bx * 64;
    const long bz = blockIdx.z;
    const int do_mirror = tri && (bx >= 2 * by + 2);

    // per-tile sources and smem base offsets (tiles: 0=Ah, 1=Al, 2=Bh, 3=Bl)
    const unsigned short* tsrc[4] = {
        Ah + bz * sA + (size_t)brow * K,
        Al + bz * sA + (size_t)brow * K,
        Bh + bz * sB + (size_t)bcol * K,
        Bl + bz * sB + (size_t)bcol * K
    };
    const uint32_t tbo[4] = {0u, A_TILE_B, 2u * A_TILE_B, 2u * A_TILE_B + B_TILE_B};

    const int NC = K >> 6;

    auto issue_i = [&](int c, int i) {
        const int un = tid + i * 256;          // 0..3071
        int tileid, u;
        if      (un < 1024) { tileid = 0; u = un; }
        else if (un < 2048) { tileid = 1; u = un - 1024; }
        else if (un < 2560) { tileid = 2; u = un - 2048; }
        else                { tileid = 3; u = un - 2560; }
        const int row = u >> 3, q = u & 7;
        const uint32_t off = (uint32_t)((row * 8 + (q ^ (row & 7))) * 16);
        cpa16(sbt + (c & 1) * STAGE_B + tbo[tileid] + off,
              tsrc[tileid] + (size_t)row * K + c * 64 + q * 8);
    };

    float acc[2][4][4];
#pragma unroll
    for (int a = 0; a < 2; a++)
#pragma unroll
        for (int b = 0; b < 4; b++)
#pragma unroll
            for (int q = 0; q < 4; q++) acc[a][b][q] = 0.f;

    const int a_r    = lane & 15;
    const int a_kbit = lane >> 4;
    const int b_r    = (lane & 7) + ((lane >> 4) << 3);
    const int b_kbit = (lane >> 3) & 1;

#pragma unroll
    for (int i = 0; i < 12; i++) issue_i(0, i);
    CP_COMMIT();

    for (int c = 0; c < NC; c++) {
        CP_WAIT(0);
        __syncthreads();

        const uint32_t stg = sbt + (c & 1) * STAGE_B;
#pragma unroll
        for (int kk = 0; kk < 4; kk++) {
            if (c + 1 < NC) {
#pragma unroll
                for (int i = kk * 3; i < kk * 3 + 3; i++) issue_i(c + 1, i);
            }
            uint32_t ah[2][4], al[2][4], bh[2][4], bl[2][4];
#pragma unroll
            for (int mt = 0; mt < 2; mt++) {
                int row = warp_m * 32 + mt * 16 + a_r;
                int ku  = kk * 2 + a_kbit;
                uint32_t off = (uint32_t)((row * 8 + (ku ^ (row & 7))) * 16);
                ldm4(ah[mt], stg + off);
                ldm4(al[mt], stg + A_TILE_B + off);
            }
#pragma unroll
            for (int p = 0; p < 2; p++) {
                int row = warp_n * 32 + p * 16 + b_r;
                int ku  = kk * 2 + b_kbit;
                uint32_t off = (uint32_t)((row * 8 + (ku ^ (row & 7))) * 16);
                ldm4(bh[p], stg + 2 * A_TILE_B + off);
                ldm4(bl[p], stg + 2 * A_TILE_B + B_TILE_B + off);
            }
#pragma unroll
            for (int mt = 0; mt < 2; mt++)
#pragma unroll
                for (int nt = 0; nt < 4; nt++) {
                    const int p = nt >> 1, q = (nt & 1) * 2;
                    mma16816(acc[mt][nt], ah[mt], bh[p][q], bh[p][q + 1]);
                    mma16816(acc[mt][nt], al[mt], bh[p][q], bh[p][q + 1]);
                    mma16816(acc[mt][nt], ah[mt], bl[p][q], bl[p][q + 1]);
                }
        }
        if (c + 1 < NC) CP_COMMIT();
    }

    // mirror staging buffers (reuse stage smem after mainloop):
    // s_h/s_l: [64 cols][130 ushorts] (128 rows + 2 pad) per array
    unsigned short* s_h = (unsigned short*)smem;
    unsigned short* s_l = s_h + 64 * 130;
    if (do_mirror) __syncthreads();   // all ldmatrix reads of stage smem done

    // epilogue
    float*          Cb  = C  ? C  + bz * sC : nullptr;
    unsigned short* Chb = Ch + bz * sC;
    unsigned short* Clb = Cl + bz * sC;
#pragma unroll
    for (int mt = 0; mt < 2; mt++)
#pragma unroll
        for (int nt = 0; nt < 4; nt++) {
            const float* dd = acc[mt][nt];
            const int rl  = warp_m * 32 + mt * 16 + (lane >> 2);
            const int cl0 = warp_n * 32 + nt * 8 + (lane & 3) * 2;
            const int r   = brow + rl;
            const int col = bcol + cl0;
            if (!split_out) {
                *(float2*)&Cb[(size_t)r * N + col]       = make_float2(dd[0], dd[1]);
                *(float2*)&Cb[(size_t)(r + 8) * N + col] = make_float2(dd[2], dd[3]);
            } else {
                unsigned short h0, l0, h1, l1;
                split1(dd[0], h0, l0); split1(dd[1], h1, l1);
                *(uint32_t*)&Chb[(size_t)r * N + col] = packus(h0, h1);
                *(uint32_t*)&Clb[(size_t)r * N + col] = packus(l0, l1);
                if (do_mirror) {
                    s_h[cl0 * 130 + rl] = h0; s_h[(cl0 + 1) * 130 + rl] = h1;
                    s_l[cl0 * 130 + rl] = l0; s_l[(cl0 + 1) * 130 + rl] = l1;
                }
                split1(dd[2], h0, l0); split1(dd[3], h1, l1);
                *(uint32_t*)&Chb[(size_t)(r + 8) * N + col] = packus(h0, h1);
                *(uint32_t*)&Clb[(size_t)(r + 8) * N + col] = packus(l0, l1);
                if (do_mirror) {
                    s_h[cl0 * 130 + rl + 8] = h0; s_h[(cl0 + 1) * 130 + rl + 8] = h1;
                    s_l[cl0 * 130 + rl + 8] = l0; s_l[(cl0 + 1) * 130 + rl + 8] = l1;
                }
            }
        }

    if (do_mirror) {
        __syncthreads();
        const uint32_t* su = (const uint32_t*)smem;   // 65 uints per 130-ushort row
#pragma unroll
        for (int i = 0; i < 16; i++) {
            const int idx = tid + i * 256;            // 0..4095
            const int cl  = idx >> 6;                 // 0..63   (output row' = bcol+cl)
            const int k   = idx & 63;                 // uint along rows (2 per uint)
            const uint32_t vh = su[cl * 65 + k];
            const uint32_t vl = su[64 * 65 + cl * 65 + k];
            *(uint32_t*)&Chb[(size_t)(bcol + cl) * N + brow + 2 * k] = vh;
            *(uint32_t*)&Clb[(size_t)(bcol + cl) * N + brow + 2 * k] = vl;
        }
    }
}

// ---------------------------------------------------------------------------
// x [B,LX,D] fp32 -> xTh/xTl [B,D,LX] bf16 hi/lo (fused transpose + split,
// packed uint32 stores; tile 64(l) x 32(d))
// ---------------------------------------------------------------------------
__global__ __launch_bounds__(256) void transpose_split_x(const float* __restrict__ x)
{
    __shared__ float t[64][33];
    const int b = blockIdx.z;
    const int lb = blockIdx.x * 64, d0 = blockIdx.y * 32;
    const int tx = threadIdx.x, ty = threadIdx.y;   // (32, 8)
    const float* xp = x + (size_t)b * LX * D;
#pragma unroll
    for (int i = 0; i < 64; i += 8)
        t[ty + i][tx] = xp[(size_t)(lb + ty + i) * D + d0 + tx];
    __syncthreads();
    const int tid = ty * 32 + tx;
#pragma unroll
    for (int i = 0; i < 4; i++) {
        const int s = tid + i * 256;        // 0..1023
        const int dd = s >> 5, lu = s & 31; // dd 0..31, lu 0..31 (pair index)
        float v0 = t[2 * lu][dd], v1 = t[2 * lu + 1][dd];
        unsigned short h0, lo0, h1, lo1;
        split1(v0, h0, lo0); split1(v1, h1, lo1);
        size_t o = ((size_t)b * D + d0 + dd) * LX + lb + 2 * lu;   // even
        *(uint32_t*)&g_xTh[o] = packus(h0, h1);
        *(uint32_t*)&g_xTl[o] = packus(lo0, lo1);
    }
}

// ---------------------------------------------------------------------------
// Fused beta + pooled partials (proven R13 version).
// ---------------------------------------------------------------------------
__global__ __launch_bounds__(256) void beta_pooled_fused(
    const float* __restrict__ mainp, const float* __restrict__ w)
{
    __shared__ float sbeta[32];
    const int b  = blockIdx.y;
    const int sp = blockIdx.x;
    const int wid = threadIdx.x >> 5, lane = threadIdx.x & 31;
    const int m0 = sp * (LM / NSPLIT);

    // phase 1: betas for 32 rows
#pragma unroll
    for (int rr = 0; rr < 4; rr++) {
        const int m = m0 + wid * 4 + rr;
        const float4* mp = (const float4*)(mainp + ((size_t)b * LM + m) * D);
        const float4* ap = (const float4*)(g_A   + ((size_t)b * LM + m) * D);
        float s = 0.f;
#pragma unroll
        for (int j = 0; j < 6; j++) {
            const int idx = lane + j * 32;
            float4 mv = mp[idx], av = ap[idx];
            float4 w1 = ((const float4*)w)[idx];
            float4 w2 = ((const float4*)(w + D))[idx];
            s += (mv.x - av.x) * w1.x + (mv.x * av.x) * w2.x;
            s += (mv.y - av.y) * w1.y + (mv.y * av.y) * w2.y;
            s += (mv.z - av.z) * w1.z + (mv.z * av.z) * w2.z;
            s += (mv.w - av.w) * w1.w + (mv.w * av.w) * w2.w;
        }
#pragma unroll
        for (int o = 16; o; o >>= 1) s += __shfl_xor_sync(0xffffffffu, s, o);
        if (lane == 0) sbeta[wid * 4 + rr] = s;
    }
    __syncthreads();

    // phase 2: weighted pooling over the same 32 rows (L2-resident)
    float ss[3] = {0.f, 0.f, 0.f}, sm[3] = {0.f, 0.f, 0.f};
    for (int i = 0; i < 32; i++) {
        const float bt = sbeta[i];
        const float* mp = mainp + ((size_t)b * LM + m0 + i) * D;
        const float* ap = g_A   + ((size_t)b * LM + m0 + i) * D;
#pragma unroll
        for (int j = 0; j < 3; j++) {
            const int d = threadIdx.x + j * 256;
            float mv = mp[d], av = ap[d];
            ss[j] += bt * (mv - av);
            sm[j] += bt * (mv * av);
        }
    }
    float* pp = g_part + (size_t)(b * NSPLIT + sp) * 2 * D;
#pragma unroll
    for (int j = 0; j < 3; j++) {
        const int d = threadIdx.x + j * 256;
        pp[d]     = ss[j];
        pp[D + d] = sm[j];
    }
}

__global__ __launch_bounds__(256) void pooled_reduce(float* __restrict__ out)
{
    const int b = blockIdx.x;
    for (int k = threadIdx.x; k < 2 * D; k += 256) {
        float s = 0.f;
#pragma unroll
        for (int sp = 0; sp < NSPLIT; sp++)
            s += g_part[(size_t)(b * NSPLIT + sp) * 2 * D + k];
        out[(size_t)b * 2 * D + k] = s;
    }
}

// ---------------------------------------------------------------------------
extern "C" void kernel_launch(void* const* d_in, const int* in_sizes, int n_in,
                              void* d_out, int out_size)
{
    const float* mainp = (const float*)d_in[0];   // (B, LM, D)
    const float* xp    = (const float*)d_in[1];   // (B, LX, D)
    const float* Wp    = (const float*)d_in[2];   // (D, D)
    const float* wp    = (const float*)d_in[3];   // (2D, 1)
    float*       out   = (float*)d_out;           // (B, 2D)

    cudaFuncSetAttribute(gemm_bf16, cudaFuncAttributeMaxDynamicSharedMemorySize, GSMEM);

    unsigned short *xTh, *xTl, *Gh, *Gl, *Ph, *Pl, *mh, *ml, *Wh, *Wl;
    float *Aout;
    cudaGetSymbolAddress((void**)&xTh, g_xTh);
    cudaGetSymbolAddress((void**)&xTl, g_xTl);
    cudaGetSymbolAddress((void**)&Gh,  g_Gh);
    cudaGetSymbolAddress((void**)&Gl,  g_Gl);
    cudaGetSymbolAddress((void**)&Ph,  g_Ph);
    cudaGetSymbolAddress((void**)&Pl,  g_Pl);
    cudaGetSymbolAddress((void**)&mh,  g_mh);
    cudaGetSymbolAddress((void**)&ml,  g_ml);
    cudaGetSymbolAddress((void**)&Wh,  g_Wh);
    cudaGetSymbolAddress((void**)&Wl,  g_Wl);
    cudaGetSymbolAddress((void**)&Aout, g_A);

    // 0) transpose+split of x (needed by GEMM1)
    transpose_split_x<<<dim3(LX / 64, D / 32, B_SZ), dim3(32, 8)>>>(xp);

    // 1) G_b = xT_b @ xT_b^T (symmetric: 42 upper 64-col blocks, fused mirror)
    //    + 14 extra blockIdx.x slots per z: fp32->bf16 splitters for main and W
    //    (fill GEMM1's idle tail-wave CTA slots; outputs consumed by G2/G3)
    gemm_bf16<<<dim3(TRI_N + XTRA, 1, B_SZ), 256, GSMEM>>>(
        xTh, xTl, xTh, xTl, nullptr, Gh, Gl,
        D, LX, (long)D * LX, (long)D * LX, (long)D * D, 1, 1,
        mainp, mh, ml, (long)B_SZ * LM * D / 4,
        Wp, Wh, Wl, D * D / 4);

    // 2) P_b = G_b @ W^T     (D x D, K = D), W broadcast, split output
    gemm_bf16<<<dim3(D / 64, D / 128, B_SZ), 256, GSMEM>>>(
        Gh, Gl, Wh, Wl, nullptr, Ph, Pl,
        D, D, (long)D * D, 0L, (long)D * D, 1, 0,
        nullptr, nullptr, nullptr, 0L, nullptr, nullptr, nullptr, 0);

    // 3) A_b = main_b @ P_b^T (LM x D, K = D), fp32 output
    gemm_bf16<<<dim3(D / 64, LM / 128, B_SZ), 256, GSMEM>>>(
        mh, ml, Ph, Pl, Aout, Ph, Pl,
        D, D, (long)LM * D, (long)D * D, (long)LM * D, 0, 0,
        nullptr, nullptr, nullptr, 0L, nullptr, nullptr, nullptr, 0);

    // 4) fused beta + pooled partials, deterministic reduce
    beta_pooled_fused<<<dim3(NSPLIT, B_SZ), 256>>>(mainp, wp);
    pooled_reduce<<<B_SZ, 256>>>(out);
}